// round 2
// baseline (speedup 1.0000x reference)
#include <cuda_runtime.h>

#define NB 4
#define NS 2048
#define NE 1024
#define NH 16
#define ND 64

// Scratch (device globals — no allocations allowed in kernel_launch)
__device__ __align__(256) float g_q[NB * NH * NS * ND];
__device__ __align__(256) float g_k[NB * NH * NS * ND];
__device__ __align__(256) float g_v[NB * NH * NS * ND];
__device__ __align__(256) float g_ctx[NB * NS * NE];

// ---------------------------------------------------------------------------
// Per-head projection GEMM:
//   out[b,h,s,d] = sum_e X[b,s,e] * W[h,e,d] + bias[h,d]
// X: [8192,1024] row-major. W: [H,E,DH]. out layout ((b*H+h)*S+s)*DH+d.
// Tile: BM=128, BN=64 (one head), BK=16; 256 threads; 8x4 per thread.
// ---------------------------------------------------------------------------
__global__ __launch_bounds__(256) void proj_kernel(
    const float* __restrict__ X,
    const float* __restrict__ W,
    const float* __restrict__ bias,
    float* __restrict__ out)
{
    __shared__ __align__(16) float As[16][128];  // [k][m], rotated-swizzle columns
    __shared__ __align__(16) float Bs[16][64];   // [k][n]

    const int m0 = blockIdx.x * 128;
    const int h  = blockIdx.y;
    const float* Wh = W + (size_t)h * NE * ND;
    const int tid = threadIdx.x;
    const int tx = tid & 15;   // n = tx*4
    const int ty = tid >> 4;   // m = ty*8

    float acc[8][4];
#pragma unroll
    for (int i = 0; i < 8; i++)
#pragma unroll
        for (int j = 0; j < 4; j++) acc[i][j] = 0.f;

    for (int k0 = 0; k0 < NE; k0 += 16) {
        // A tile: 128x16 = 512 float4 loads, 2 per thread; store transposed
        // with column rotation col' = (m + 4*(k>>2)) & 127 (bank-conflict fix).
#pragma unroll
        for (int rep = 0; rep < 2; rep++) {
            int idx = tid + rep * 256;
            int m   = idx >> 2;
            int kk4 = (idx & 3) << 2;
            float4 a = *(const float4*)&X[(size_t)(m0 + m) * NE + k0 + kk4];
            int col = (m + kk4) & 127;
            As[kk4 + 0][col] = a.x;
            As[kk4 + 1][col] = a.y;
            As[kk4 + 2][col] = a.z;
            As[kk4 + 3][col] = a.w;
        }
        // B tile: 16x64 floats, natural layout, 1 float4 per thread
        {
            int kk = tid >> 4;
            int n4 = (tid & 15) << 2;
            *(float4*)&Bs[kk][n4] =
                *(const float4*)&Wh[(size_t)(k0 + kk) * ND + n4];
        }
        __syncthreads();

#pragma unroll
        for (int kk = 0; kk < 16; kk++) {
            const int rot = kk & ~3;
            float av[8], bv[4];
            *(float4*)&av[0] = *(const float4*)&As[kk][(ty * 8 + rot) & 127];
            *(float4*)&av[4] = *(const float4*)&As[kk][(ty * 8 + 4 + rot) & 127];
            *(float4*)&bv[0] = *(const float4*)&Bs[kk][tx * 4];
#pragma unroll
            for (int i = 0; i < 8; i++)
#pragma unroll
                for (int j = 0; j < 4; j++)
                    acc[i][j] += av[i] * bv[j];
        }
        __syncthreads();
    }

    float4 bb = *(const float4*)&bias[h * ND + tx * 4];
#pragma unroll
    for (int i = 0; i < 8; i++) {
        int m = m0 + ty * 8 + i;
        int b = m >> 11;            // S = 2048
        int s = m & (NS - 1);
        float4 r;
        r.x = acc[i][0] + bb.x;
        r.y = acc[i][1] + bb.y;
        r.z = acc[i][2] + bb.z;
        r.w = acc[i][3] + bb.w;
        *(float4*)&out[((size_t)(b * NH + h) * NS + s) * ND + tx * 4] = r;
    }
}

// ---------------------------------------------------------------------------
// Output projection GEMM: out[m,n] = sum_k ctx[m,k]*Wo[k,n] + bo[n]
// ctx: [8192,1024], Wo: [1024,1024] row-major.
// ---------------------------------------------------------------------------
__global__ __launch_bounds__(256) void outproj_kernel(
    const float* __restrict__ X,
    const float* __restrict__ W,
    const float* __restrict__ bias,
    float* __restrict__ out)
{
    __shared__ __align__(16) float As[16][128];
    __shared__ __align__(16) float Bs[16][64];

    const int m0 = blockIdx.x * 128;
    const int n0 = blockIdx.y * 64;
    const int tid = threadIdx.x;
    const int tx = tid & 15;
    const int ty = tid >> 4;

    float acc[8][4];
#pragma unroll
    for (int i = 0; i < 8; i++)
#pragma unroll
        for (int j = 0; j < 4; j++) acc[i][j] = 0.f;

    for (int k0 = 0; k0 < NE; k0 += 16) {
#pragma unroll
        for (int rep = 0; rep < 2; rep++) {
            int idx = tid + rep * 256;
            int m   = idx >> 2;
            int kk4 = (idx & 3) << 2;
            float4 a = *(const float4*)&X[(size_t)(m0 + m) * NE + k0 + kk4];
            int col = (m + kk4) & 127;
            As[kk4 + 0][col] = a.x;
            As[kk4 + 1][col] = a.y;
            As[kk4 + 2][col] = a.z;
            As[kk4 + 3][col] = a.w;
        }
        {
            int kk = tid >> 4;
            int n4 = (tid & 15) << 2;
            *(float4*)&Bs[kk][n4] =
                *(const float4*)&W[(size_t)(k0 + kk) * NE + n0 + n4];
        }
        __syncthreads();

#pragma unroll
        for (int kk = 0; kk < 16; kk++) {
            const int rot = kk & ~3;
            float av[8], bv[4];
            *(float4*)&av[0] = *(const float4*)&As[kk][(ty * 8 + rot) & 127];
            *(float4*)&av[4] = *(const float4*)&As[kk][(ty * 8 + 4 + rot) & 127];
            *(float4*)&bv[0] = *(const float4*)&Bs[kk][tx * 4];
#pragma unroll
            for (int i = 0; i < 8; i++)
#pragma unroll
                for (int j = 0; j < 4; j++)
                    acc[i][j] += av[i] * bv[j];
        }
        __syncthreads();
    }

    float4 bb = *(const float4*)&bias[n0 + tx * 4];
#pragma unroll
    for (int i = 0; i < 8; i++) {
        int m = m0 + ty * 8 + i;
        float4 r;
        r.x = acc[i][0] + bb.x;
        r.y = acc[i][1] + bb.y;
        r.z = acc[i][2] + bb.z;
        r.w = acc[i][3] + bb.w;
        *(float4*)&out[(size_t)m * NE + n0 + tx * 4] = r;
    }
}

// ---------------------------------------------------------------------------
// Flash attention (fp32): per (b,h), 64-query tile, loop over 64-key tiles.
// scores = q@k^T * 0.125 + bias[s,t]; online softmax; ctx written to
// (B, S, H*DH) layout so outproj is a plain GEMM.
// blockDim = 128: tx in [0,8) owns cols {tx*4..+3, tx*4+32..+35}; ty in [0,16)
// owns rows ty*4..+3. 48 KB static smem -> 4 CTAs/SM.
// ---------------------------------------------------------------------------
__global__ __launch_bounds__(128) void attn_kernel(
    const float* __restrict__ q,
    const float* __restrict__ k,
    const float* __restrict__ v,
    const float* __restrict__ bias,
    float* __restrict__ ctx)
{
    // Qt/KPs hold transposed [d][r or t] tiles with rotation swizzle
    // col' = (r + 4*(d>>2)) & 63. KPs is re-used for P[r][t] (plain layout).
    __shared__ __align__(16) float Qt[64][64];
    __shared__ __align__(16) float KPs[64][64];
    __shared__ __align__(16) float Vs[64][64];

    const int s0 = blockIdx.x * 64;
    const int bh = blockIdx.y;
    const float* qp = q + (size_t)bh * NS * ND;
    const float* kp = k + (size_t)bh * NS * ND;
    const float* vp = v + (size_t)bh * NS * ND;
    const int tid = threadIdx.x;
    const int tx = tid & 7;
    const int ty = tid >> 3;
    const int tx4 = tx * 4;
    const int ty4 = ty * 4;

    // Load Q tile transposed+swizzled (coalesced global float4 reads)
#pragma unroll
    for (int rep = 0; rep < 8; rep++) {
        int idx = tid + rep * 128;
        int r  = idx >> 4;
        int d4 = (idx & 15) << 2;
        float4 a = *(const float4*)&qp[(size_t)(s0 + r) * ND + d4];
        int col = (r + d4) & 63;
        Qt[d4 + 0][col] = a.x;
        Qt[d4 + 1][col] = a.y;
        Qt[d4 + 2][col] = a.z;
        Qt[d4 + 3][col] = a.w;
    }

    float o[4][8];
    float mrow[4], lrow[4];
#pragma unroll
    for (int i = 0; i < 4; i++) {
        mrow[i] = -1e30f;
        lrow[i] = 0.f;
#pragma unroll
        for (int j = 0; j < 8; j++) o[i][j] = 0.f;
    }

    for (int t0 = 0; t0 < NS; t0 += 64) {
        __syncthreads();  // prior iter done with KPs(P) and Vs; Qt visible
        // Load K (transposed+swizzled) and V (natural) tiles.
        // 64 rows x 16 float4 per operand = 1024 float4 each -> 8 reps x 128 thr.
#pragma unroll
        for (int rep = 0; rep < 8; rep++) {
            int idx = tid + rep * 128;
            int t  = idx >> 4;
            int d4 = (idx & 15) << 2;
            float4 a = *(const float4*)&kp[(size_t)(t0 + t) * ND + d4];
            int col = (t + d4) & 63;
            KPs[d4 + 0][col] = a.x;
            KPs[d4 + 1][col] = a.y;
            KPs[d4 + 2][col] = a.z;
            KPs[d4 + 3][col] = a.w;
            *(float4*)&Vs[t][d4] =
                *(const float4*)&vp[(size_t)(t0 + t) * ND + d4];
        }
        __syncthreads();

        // scores tile: sc[i][j] over d (j<4 -> t=tx4+j ; j>=4 -> t=tx4+32+j-4)
        float sc[4][8];
#pragma unroll
        for (int i = 0; i < 4; i++)
#pragma unroll
            for (int j = 0; j < 8; j++) sc[i][j] = 0.f;

#pragma unroll 16
        for (int d = 0; d < 64; d++) {
            const int rot = d & ~3;
            float av[4], bv[8];
            *(float4*)&av[0] = *(const float4*)&Qt[d][(ty4 + rot) & 63];
            *(float4*)&bv[0] = *(const float4*)&KPs[d][(tx4 + rot) & 63];
            *(float4*)&bv[4] = *(const float4*)&KPs[d][(tx4 + 32 + rot) & 63];
#pragma unroll
            for (int i = 0; i < 4; i++)
#pragma unroll
                for (int j = 0; j < 8; j++)
                    sc[i][j] += av[i] * bv[j];
        }

        // scale + bias (L2-resident)
#pragma unroll
        for (int i = 0; i < 4; i++) {
            const float* bp = &bias[(size_t)(s0 + ty4 + i) * NS + t0];
            float4 b0 = *(const float4*)&bp[tx4];
            float4 b1 = *(const float4*)&bp[tx4 + 32];
            sc[i][0] = sc[i][0] * 0.125f + b0.x;
            sc[i][1] = sc[i][1] * 0.125f + b0.y;
            sc[i][2] = sc[i][2] * 0.125f + b0.z;
            sc[i][3] = sc[i][3] * 0.125f + b0.w;
            sc[i][4] = sc[i][4] * 0.125f + b1.x;
            sc[i][5] = sc[i][5] * 0.125f + b1.y;
            sc[i][6] = sc[i][6] * 0.125f + b1.z;
            sc[i][7] = sc[i][7] * 0.125f + b1.w;
        }

        // online softmax stats (row reduction across the 8 tx lanes)
        float alpha[4];
#pragma unroll
        for (int i = 0; i < 4; i++) {
            float mt = sc[i][0];
#pragma unroll
            for (int j = 1; j < 8; j++) mt = fmaxf(mt, sc[i][j]);
#pragma unroll
            for (int off = 1; off < 8; off <<= 1)
                mt = fmaxf(mt, __shfl_xor_sync(0xffffffffu, mt, off));
            float mnew = fmaxf(mrow[i], mt);
            alpha[i] = __expf(mrow[i] - mnew);
            mrow[i] = mnew;
            float rs = 0.f;
#pragma unroll
            for (int j = 0; j < 8; j++) {
                sc[i][j] = __expf(sc[i][j] - mnew);
                rs += sc[i][j];
            }
#pragma unroll
            for (int off = 1; off < 8; off <<= 1)
                rs += __shfl_xor_sync(0xffffffffu, rs, off);
            lrow[i] = lrow[i] * alpha[i] + rs;
        }

        __syncthreads();  // everyone done reading KPs as K
        // store P[r][t] into KPs (plain layout, float4, phase-conflict-free)
#pragma unroll
        for (int i = 0; i < 4; i++) {
            float4 p0 = make_float4(sc[i][0], sc[i][1], sc[i][2], sc[i][3]);
            float4 p1 = make_float4(sc[i][4], sc[i][5], sc[i][6], sc[i][7]);
            *(float4*)&KPs[ty4 + i][tx4] = p0;
            *(float4*)&KPs[ty4 + i][tx4 + 32] = p1;
        }
        __syncthreads();

#pragma unroll
        for (int i = 0; i < 4; i++)
#pragma unroll
            for (int j = 0; j < 8; j++) o[i][j] *= alpha[i];

        // o += P @ V
#pragma unroll
        for (int t4 = 0; t4 < 64; t4 += 4) {
            float a[4][4];
#pragma unroll
            for (int i = 0; i < 4; i++)
                *(float4*)&a[i][0] = *(const float4*)&KPs[ty4 + i][t4];
#pragma unroll
            for (int c = 0; c < 4; c++) {
                float vv[8];
                *(float4*)&vv[0] = *(const float4*)&Vs[t4 + c][tx4];
                *(float4*)&vv[4] = *(const float4*)&Vs[t4 + c][tx4 + 32];
#pragma unroll
                for (int i = 0; i < 4; i++)
#pragma unroll
                    for (int j = 0; j < 8; j++)
                        o[i][j] += a[i][c] * vv[j];
            }
        }
    }

    // normalize and write ctx in (B, S, H*DH) layout
    const int b = bh >> 4;
    const int h = bh & 15;
#pragma unroll
    for (int i = 0; i < 4; i++) {
        float inv = 1.f / lrow[i];
        size_t base = ((size_t)b * NS + s0 + ty4 + i) * NE + h * ND;
        float4 r0 = make_float4(o[i][0] * inv, o[i][1] * inv,
                                o[i][2] * inv, o[i][3] * inv);
        float4 r1 = make_float4(o[i][4] * inv, o[i][5] * inv,
                                o[i][6] * inv, o[i][7] * inv);
        *(float4*)&ctx[base + tx4] = r0;
        *(float4*)&ctx[base + tx4 + 32] = r1;
    }
}

// ---------------------------------------------------------------------------

extern "C" void kernel_launch(void* const* d_in, const int* in_sizes, int n_in,
                              void* d_out, int out_size)
{
    const float* query = (const float*)d_in[0];
    const float* key_  = (const float*)d_in[1];
    const float* value = (const float*)d_in[2];
    const float* abias = (const float*)d_in[3];
    const float* Wq = (const float*)d_in[4];
    const float* bq = (const float*)d_in[5];
    const float* Wk = (const float*)d_in[6];
    const float* bk = (const float*)d_in[7];
    const float* Wv = (const float*)d_in[8];
    const float* bv = (const float*)d_in[9];
    const float* Wo = (const float*)d_in[10];
    const float* bo = (const float*)d_in[11];
    float* out = (float*)d_out;

    float *qp, *kp, *vp, *cp;
    cudaGetSymbolAddress((void**)&qp, g_q);
    cudaGetSymbolAddress((void**)&kp, g_k);
    cudaGetSymbolAddress((void**)&vp, g_v);
    cudaGetSymbolAddress((void**)&cp, g_ctx);

    dim3 gproj(64, 16);   // M/128 x H
    proj_kernel<<<gproj, 256>>>(query, Wq, bq, qp);
    proj_kernel<<<gproj, 256>>>(key_,  Wk, bk, kp);
    proj_kernel<<<gproj, 256>>>(value, Wv, bv, vp);

    dim3 gattn(32, 64);   // S/64 x (B*H)
    attn_kernel<<<gattn, 128>>>(qp, kp, vp, abias, cp);

    dim3 gout(64, 16);    // M/128 x N/64
    outproj_kernel<<<gout, 256>>>(cp, Wo, bo, out);
}

// round 4
// speedup vs baseline: 1.3997x; 1.3997x over previous
#include <cuda_runtime.h>
#include <cuda_bf16.h>
#include <cstdint>

#define NB 4
#define NS 2048
#define NE 1024
#define NH 16
#define ND 64

// Arch-specific feature gate: tcgen05 asm may only be emitted in the
// sm_103a compilation pass, not the compute_103 (base) PTX pass.
#if defined(__CUDA_ARCH__) && (defined(__CUDA_ARCH_FEAT_SM103_ALL) || \
    (defined(__CUDA_ARCH_SPECIFIC__)))
#define HAS_TCGEN05 1
#else
#define HAS_TCGEN05 0
#endif

// ---------------------------------------------------------------------------
// Device globals (scratch)
// ---------------------------------------------------------------------------
__device__ __align__(256) float g_q[NB * NH * NS * ND];
__device__ __align__(256) float g_k[NB * NH * NS * ND];
__device__ __align__(256) float g_v[NB * NH * NS * ND];
__device__ __align__(256) float g_ctx[NB * NS * NE];
__device__ __align__(256) __nv_bfloat16 g_ah[NB * NS * NE];
__device__ __align__(256) __nv_bfloat16 g_al[NB * NS * NE];
__device__ __align__(256) __nv_bfloat16 g_wth[NE * NE];
__device__ __align__(256) __nv_bfloat16 g_wtl[NE * NE];
__device__ int g_use_tc;

// ---------------------------------------------------------------------------
// Probe: records (deterministically, per selected cubin) whether the
// tcgen05 path is compiled in.
// ---------------------------------------------------------------------------
__global__ void probe_kernel() { g_use_tc = HAS_TCGEN05; }

// ---------------------------------------------------------------------------
// PTX helpers (only referenced inside HAS_TCGEN05-guarded code)
// ---------------------------------------------------------------------------
__device__ __forceinline__ uint32_t smem_u32(const void* p) {
    uint32_t a;
    asm("{ .reg .u64 t; cvta.to.shared.u64 t, %1; cvt.u32.u64 %0, t; }"
        : "=r"(a) : "l"(p));
    return a;
}
__device__ __forceinline__ uint32_t elect_one() {
    uint32_t pred;
    asm volatile("{ .reg .pred p; elect.sync _|p, 0xFFFFFFFF; selp.b32 %0,1,0,p; }"
                 : "=r"(pred));
    return pred;
}
#define MBARRIER_INIT(addr, cnt) \
    asm volatile("mbarrier.init.shared.b64 [%0], %1;" :: "r"(addr), "r"(cnt) : "memory")
#define MBARRIER_WAIT_PARITY(addr, par) do {                                   \
    uint32_t _m = (addr), _p = (par), _d;                                      \
    asm volatile("{ .reg .pred p; mbarrier.try_wait.parity.acquire.cta.shared::cta.b64 p, [%1], %2; selp.b32 %0,1,0,p; }" \
        : "=r"(_d) : "r"(_m), "r"(_p) : "memory");                             \
    if (!_d) {                                                                 \
        asm volatile("{ .reg .pred P1; WL_%=: mbarrier.try_wait.parity.acquire.cta.shared::cta.b64 P1, [%0], %1, 0x989680; @P1 bra.uni WD_%=; bra.uni WL_%=; WD_%=: }" \
            :: "r"(_m), "r"(_p) : "memory");                                   \
    } } while (0)
#define TCGEN05_ALLOC(saddr, ncols) \
    asm volatile("tcgen05.alloc.cta_group::1.sync.aligned.shared::cta.b32 [%0], %1;" \
        :: "r"((uint32_t)(saddr)), "r"((uint32_t)(ncols)) : "memory")
#define TCGEN05_DEALLOC(tmem, ncols) \
    asm volatile("tcgen05.dealloc.cta_group::1.sync.aligned.b32 %0, %1;" \
        :: "r"(tmem), "r"((uint32_t)(ncols)))
#define TCGEN05_COMMIT(mbar) \
    asm volatile("tcgen05.commit.cta_group::1.mbarrier::arrive::one.shared::cluster.b64 [%0];" \
        :: "r"((uint32_t)(mbar)) : "memory")
#define TCGEN05_WAIT_LD() asm volatile("tcgen05.wait::ld.sync.aligned;" ::: "memory")
#define TCGEN05_FENCE_AFTER() asm volatile("tcgen05.fence::after_thread_sync;" ::: "memory")
#define FENCE_ASYNC() asm volatile("fence.proxy.async.shared::cta;" ::: "memory")

#define TCGEN05_LD_X32(r, ta)                                                  \
    asm volatile("tcgen05.ld.sync.aligned.32x32b.x32.b32 "                     \
        "{%0,%1,%2,%3,%4,%5,%6,%7,%8,%9,%10,%11,%12,%13,%14,%15,"             \
        "%16,%17,%18,%19,%20,%21,%22,%23,%24,%25,%26,%27,%28,%29,%30,%31}, [%32];" \
        : "=r"((r)[0]),"=r"((r)[1]),"=r"((r)[2]),"=r"((r)[3]),                 \
          "=r"((r)[4]),"=r"((r)[5]),"=r"((r)[6]),"=r"((r)[7]),                 \
          "=r"((r)[8]),"=r"((r)[9]),"=r"((r)[10]),"=r"((r)[11]),               \
          "=r"((r)[12]),"=r"((r)[13]),"=r"((r)[14]),"=r"((r)[15]),             \
          "=r"((r)[16]),"=r"((r)[17]),"=r"((r)[18]),"=r"((r)[19]),             \
          "=r"((r)[20]),"=r"((r)[21]),"=r"((r)[22]),"=r"((r)[23]),             \
          "=r"((r)[24]),"=r"((r)[25]),"=r"((r)[26]),"=r"((r)[27]),             \
          "=r"((r)[28]),"=r"((r)[29]),"=r"((r)[30]),"=r"((r)[31])              \
        : "r"(ta))

#if HAS_TCGEN05
__device__ __forceinline__ uint64_t make_desc(uint32_t addr) {
    const uint64_t base = (uint64_t(2) << 61) | (uint64_t(1) << 46) |
                          (uint64_t(64) << 32) | (uint64_t(1) << 16);
    return base | ((uint64_t)(addr >> 4) & 0x3FFF);
}
__device__ __forceinline__ void mma_f16_ss(uint32_t d, uint64_t a, uint64_t b,
                                           uint32_t idesc, uint32_t en) {
    asm volatile(
        "{ .reg .pred p; setp.ne.u32 p, %4, 0;\n\t"
        "tcgen05.mma.cta_group::1.kind::f16 [%0], %1, %2, %3, {%5,%5,%5,%5}, p; }"
        :: "r"(d), "l"(a), "l"(b), "r"(idesc), "r"(en), "r"(0u) : "memory");
}
#endif

#define GEMM_MT 128
#define GEMM_NT 256
#define GEMM_KC 64
#define GEMM_NCHUNK (NE / GEMM_KC)
#define GEMM_IDESC ((1u<<4)|(1u<<7)|(1u<<10)|((GEMM_NT/8)<<17)|((GEMM_MT/16)<<24))
#define GEMM_BUF_BYTES 98304
#define GEMM_SMEM_BYTES (1024 + 2 * GEMM_BUF_BYTES)

template <int NIT>
__device__ __forceinline__ void ld_tile(const __nv_bfloat16* __restrict__ g,
                                        size_t row0, char* s, int tid) {
#pragma unroll
    for (int it = 0; it < NIT; it++) {
        int idx = tid + it * 128;
        int row = idx >> 3, q = idx & 7;
        uint4 v = *((const uint4*)(g + (row0 + row) * NE) + q);
        uint32_t off = (uint32_t)(row * 128 + q * 16);
        off ^= (off >> 3) & 0x70;
        *(uint4*)(s + off) = v;
    }
}

// ---------------------------------------------------------------------------
// tcgen05 GEMM (sm_103a pass only): out[8192,1024] = A * B^T + bias.
// A = Ah+Al bf16 split; 3-term split MMA. mode 0 -> q/k/v layout; mode 1 flat.
// ---------------------------------------------------------------------------
__global__ __launch_bounds__(128) void gemm_mma_kernel(
    const __nv_bfloat16* __restrict__ Ah, const __nv_bfloat16* __restrict__ Al,
    const __nv_bfloat16* __restrict__ Bh, const __nv_bfloat16* __restrict__ Bl,
    const float* __restrict__ bias, float* __restrict__ outp, int mode)
{
#if HAS_TCGEN05
    extern __shared__ __align__(1024) char smem[];
    const uint32_t sb = smem_u32(smem);
    const int tid = threadIdx.x;
    const int wid = tid >> 5, lid = tid & 31;
    const int m0 = blockIdx.x * GEMM_MT;
    const int n0 = blockIdx.y * GEMM_NT;

    if (wid == 0) TCGEN05_ALLOC(sb, 512);
    if (tid == 0) { MBARRIER_INIT(sb + 16, 1); MBARRIER_INIT(sb + 24, 1); }
    __syncthreads();
    uint32_t tmem;
    asm volatile("ld.shared.b32 %0, [%1];" : "=r"(tmem) : "r"(sb));

    int ph0 = 0, ph1 = 0;
    for (int c = 0; c < GEMM_NCHUNK; c++) {
        const int buf = c & 1;
        char* bs = smem + 1024 + buf * GEMM_BUF_BYTES;
        if (c >= 2) {
            if (buf == 0) { MBARRIER_WAIT_PARITY(sb + 16, ph0); ph0 ^= 1; }
            else          { MBARRIER_WAIT_PARITY(sb + 24, ph1); ph1 ^= 1; }
        }
        const int k0 = c * GEMM_KC;
        ld_tile<8>(Ah + k0, (size_t)m0, bs, tid);
        ld_tile<8>(Al + k0, (size_t)m0, bs + 16384, tid);
        ld_tile<16>(Bh + k0, (size_t)n0, bs + 32768, tid);
        ld_tile<16>(Bl + k0, (size_t)n0, bs + 65536, tid);
        __syncthreads();

        if (wid == 0 && elect_one()) {
            FENCE_ASYNC();
            const uint32_t ba = sb + 1024 + buf * GEMM_BUF_BYTES;
            uint64_t ah = make_desc(ba);
            uint64_t al = make_desc(ba + 16384);
            uint64_t bh = make_desc(ba + 32768);
            uint64_t bl = make_desc(ba + 65536);
#pragma unroll
            for (int s = 0; s < 4; s++) {
                uint64_t o2 = 2u * s;
                mma_f16_ss(tmem, ah + o2, bh + o2, GEMM_IDESC,
                           (c > 0 || s > 0) ? 1u : 0u);
                mma_f16_ss(tmem, al + o2, bh + o2, GEMM_IDESC, 1u);
                mma_f16_ss(tmem, ah + o2, bl + o2, GEMM_IDESC, 1u);
            }
            TCGEN05_COMMIT(sb + 16 + buf * 8);
        }
    }
    MBARRIER_WAIT_PARITY(sb + 16, ph0);
    MBARRIER_WAIT_PARITY(sb + 24, ph1);
    TCGEN05_FENCE_AFTER();

    const int m = m0 + wid * 32 + lid;
    const int b = m >> 11, s_ = m & (NS - 1);
#pragma unroll
    for (int g = 0; g < 8; g++) {
        uint32_t r[32];
        TCGEN05_LD_X32(r, tmem + g * 32);
        TCGEN05_WAIT_LD();
        const int nbase = n0 + g * 32;
        float* dst;
        if (mode == 0) {
            int h = nbase >> 6, d0 = nbase & 63;
            dst = outp + (((size_t)(b * NH + h) * NS + s_) * ND + d0);
        } else {
            dst = outp + ((size_t)m * NE + nbase);
        }
#pragma unroll
        for (int j = 0; j < 32; j += 4) {
            float4 w;
            w.x = __uint_as_float(r[j + 0]) + bias[nbase + j + 0];
            w.y = __uint_as_float(r[j + 1]) + bias[nbase + j + 1];
            w.z = __uint_as_float(r[j + 2]) + bias[nbase + j + 2];
            w.w = __uint_as_float(r[j + 3]) + bias[nbase + j + 3];
            *(float4*)(dst + j) = w;
        }
    }

    __syncthreads();
    if (wid == 0) TCGEN05_DEALLOC(tmem, 512);
#else
    // base-target pass: no tensor path; fp32 fallback kernels do the work
    (void)Ah; (void)Al; (void)Bh; (void)Bl; (void)bias; (void)outp; (void)mode;
#endif
}

// ---------------------------------------------------------------------------
// fp32 -> bf16 hi/lo split (elementwise)
// ---------------------------------------------------------------------------
__global__ __launch_bounds__(256) void split_kernel(
    const float* __restrict__ x, __nv_bfloat16* __restrict__ hh,
    __nv_bfloat16* __restrict__ ll)
{
    int i = blockIdx.x * 256 + threadIdx.x;
    float4 v = ((const float4*)x)[i];
    __nv_bfloat16 h0 = __float2bfloat16(v.x);
    __nv_bfloat16 h1 = __float2bfloat16(v.y);
    __nv_bfloat16 h2 = __float2bfloat16(v.z);
    __nv_bfloat16 h3 = __float2bfloat16(v.w);
    __nv_bfloat16 l0 = __float2bfloat16(v.x - __bfloat162float(h0));
    __nv_bfloat16 l1 = __float2bfloat16(v.y - __bfloat162float(h1));
    __nv_bfloat16 l2 = __float2bfloat16(v.z - __bfloat162float(h2));
    __nv_bfloat16 l3 = __float2bfloat16(v.w - __bfloat162float(h3));
    ((__nv_bfloat162*)hh)[2 * i]     = __nv_bfloat162(h0, h1);
    ((__nv_bfloat162*)hh)[2 * i + 1] = __nv_bfloat162(h2, h3);
    ((__nv_bfloat162*)ll)[2 * i]     = __nv_bfloat162(l0, l1);
    ((__nv_bfloat162*)ll)[2 * i + 1] = __nv_bfloat162(l2, l3);
}

// ---------------------------------------------------------------------------
// transpose + split: in[z][1024][C] fp32 -> out[(z*C + c)][1024] bf16 hi/lo
// ---------------------------------------------------------------------------
__global__ __launch_bounds__(256) void transpose_split_kernel(
    const float* __restrict__ in, __nv_bfloat16* __restrict__ oh,
    __nv_bfloat16* __restrict__ ol, int C)
{
    __shared__ float t[64][65];
    const float* inz = in + (size_t)blockIdx.z * NE * C;
    const int r0 = blockIdx.x * 64, c0 = blockIdx.y * 64;
    const int tid = threadIdx.x;
#pragma unroll
    for (int it = 0; it < 16; it++) {
        int idx = tid + it * 256;
        int rr = idx >> 6, cc = idx & 63;
        t[rr][cc] = inz[(size_t)(r0 + rr) * C + c0 + cc];
    }
    __syncthreads();
#pragma unroll
    for (int it = 0; it < 16; it++) {
        int idx = tid + it * 256;
        int cc = idx >> 6, rr = idx & 63;
        float x = t[rr][cc];
        __nv_bfloat16 hi = __float2bfloat16(x);
        __nv_bfloat16 lo = __float2bfloat16(x - __bfloat162float(hi));
        size_t o = (size_t)(blockIdx.z * C + c0 + cc) * NE + r0 + rr;
        oh[o] = hi;
        ol[o] = lo;
    }
}

// ---------------------------------------------------------------------------
// fp32 fallback projection GEMM (early-exits when tcgen05 path is active)
// ---------------------------------------------------------------------------
__global__ __launch_bounds__(256) void proj_kernel(
    const float* __restrict__ X,
    const float* __restrict__ W,
    const float* __restrict__ bias,
    float* __restrict__ out)
{
    if (g_use_tc) return;
    __shared__ __align__(16) float As[16][128];
    __shared__ __align__(16) float Bs[16][64];

    const int m0 = blockIdx.x * 128;
    const int h  = blockIdx.y;
    const float* Wh = W + (size_t)h * NE * ND;
    const int tid = threadIdx.x;
    const int tx = tid & 15;
    const int ty = tid >> 4;

    float acc[8][4];
#pragma unroll
    for (int i = 0; i < 8; i++)
#pragma unroll
        for (int j = 0; j < 4; j++) acc[i][j] = 0.f;

    for (int k0 = 0; k0 < NE; k0 += 16) {
#pragma unroll
        for (int rep = 0; rep < 2; rep++) {
            int idx = tid + rep * 256;
            int m   = idx >> 2;
            int kk4 = (idx & 3) << 2;
            float4 a = *(const float4*)&X[(size_t)(m0 + m) * NE + k0 + kk4];
            int col = (m + kk4) & 127;
            As[kk4 + 0][col] = a.x;
            As[kk4 + 1][col] = a.y;
            As[kk4 + 2][col] = a.z;
            As[kk4 + 3][col] = a.w;
        }
        {
            int kk = tid >> 4;
            int n4 = (tid & 15) << 2;
            *(float4*)&Bs[kk][n4] =
                *(const float4*)&Wh[(size_t)(k0 + kk) * ND + n4];
        }
        __syncthreads();

#pragma unroll
        for (int kk = 0; kk < 16; kk++) {
            const int rot = kk & ~3;
            float av[8], bv[4];
            *(float4*)&av[0] = *(const float4*)&As[kk][(ty * 8 + rot) & 127];
            *(float4*)&av[4] = *(const float4*)&As[kk][(ty * 8 + 4 + rot) & 127];
            *(float4*)&bv[0] = *(const float4*)&Bs[kk][tx * 4];
#pragma unroll
            for (int i = 0; i < 8; i++)
#pragma unroll
                for (int j = 0; j < 4; j++)
                    acc[i][j] += av[i] * bv[j];
        }
        __syncthreads();
    }

    float4 bb = *(const float4*)&bias[h * ND + tx * 4];
#pragma unroll
    for (int i = 0; i < 8; i++) {
        int m = m0 + ty * 8 + i;
        int b = m >> 11;
        int s = m & (NS - 1);
        float4 r;
        r.x = acc[i][0] + bb.x;
        r.y = acc[i][1] + bb.y;
        r.z = acc[i][2] + bb.z;
        r.w = acc[i][3] + bb.w;
        *(float4*)&out[((size_t)(b * NH + h) * NS + s) * ND + tx * 4] = r;
    }
}

// ---------------------------------------------------------------------------
// fp32 fallback output projection (early-exits when tcgen05 path is active)
// ---------------------------------------------------------------------------
__global__ __launch_bounds__(256) void outproj_kernel(
    const float* __restrict__ X,
    const float* __restrict__ W,
    const float* __restrict__ bias,
    float* __restrict__ out)
{
    if (g_use_tc) return;
    __shared__ __align__(16) float As[16][128];
    __shared__ __align__(16) float Bs[16][64];

    const int m0 = blockIdx.x * 128;
    const int n0 = blockIdx.y * 64;
    const int tid = threadIdx.x;
    const int tx = tid & 15;
    const int ty = tid >> 4;

    float acc[8][4];
#pragma unroll
    for (int i = 0; i < 8; i++)
#pragma unroll
        for (int j = 0; j < 4; j++) acc[i][j] = 0.f;

    for (int k0 = 0; k0 < NE; k0 += 16) {
#pragma unroll
        for (int rep = 0; rep < 2; rep++) {
            int idx = tid + rep * 256;
            int m   = idx >> 2;
            int kk4 = (idx & 3) << 2;
            float4 a = *(const float4*)&X[(size_t)(m0 + m) * NE + k0 + kk4];
            int col = (m + kk4) & 127;
            As[kk4 + 0][col] = a.x;
            As[kk4 + 1][col] = a.y;
            As[kk4 + 2][col] = a.z;
            As[kk4 + 3][col] = a.w;
        }
        {
            int kk = tid >> 4;
            int n4 = (tid & 15) << 2;
            *(float4*)&Bs[kk][n4] =
                *(const float4*)&W[(size_t)(k0 + kk) * NE + n0 + n4];
        }
        __syncthreads();

#pragma unroll
        for (int kk = 0; kk < 16; kk++) {
            const int rot = kk & ~3;
            float av[8], bv[4];
            *(float4*)&av[0] = *(const float4*)&As[kk][(ty * 8 + rot) & 127];
            *(float4*)&av[4] = *(const float4*)&As[kk][(ty * 8 + 4 + rot) & 127];
            *(float4*)&bv[0] = *(const float4*)&Bs[kk][tx * 4];
#pragma unroll
            for (int i = 0; i < 8; i++)
#pragma unroll
                for (int j = 0; j < 4; j++)
                    acc[i][j] += av[i] * bv[j];
        }
        __syncthreads();
    }

    float4 bb = *(const float4*)&bias[n0 + tx * 4];
#pragma unroll
    for (int i = 0; i < 8; i++) {
        int m = m0 + ty * 8 + i;
        float4 r;
        r.x = acc[i][0] + bb.x;
        r.y = acc[i][1] + bb.y;
        r.z = acc[i][2] + bb.z;
        r.w = acc[i][3] + bb.w;
        *(float4*)&out[(size_t)m * NE + n0 + tx * 4] = r;
    }
}

// ---------------------------------------------------------------------------
// Flash attention (fp32) — shared by both paths. Writes ctx as fp32 (for the
// fp32 fallback outproj) and as bf16 hi/lo (for the tcgen05 outproj).
// ---------------------------------------------------------------------------
__global__ __launch_bounds__(128) void attn_kernel(
    const float* __restrict__ q,
    const float* __restrict__ k,
    const float* __restrict__ v,
    const float* __restrict__ bias,
    float* __restrict__ ctx,
    __nv_bfloat16* __restrict__ ctx_h,
    __nv_bfloat16* __restrict__ ctx_l)
{
    __shared__ __align__(16) float Qt[64][64];
    __shared__ __align__(16) float KPs[64][64];
    __shared__ __align__(16) float Vs[64][64];

    const int s0 = blockIdx.x * 64;
    const int bh = blockIdx.y;
    const float* qp = q + (size_t)bh * NS * ND;
    const float* kp = k + (size_t)bh * NS * ND;
    const float* vp = v + (size_t)bh * NS * ND;
    const int tid = threadIdx.x;
    const int tx = tid & 7;
    const int ty = tid >> 3;
    const int tx4 = tx * 4;
    const int ty4 = ty * 4;

#pragma unroll
    for (int rep = 0; rep < 8; rep++) {
        int idx = tid + rep * 128;
        int r  = idx >> 4;
        int d4 = (idx & 15) << 2;
        float4 a = *(const float4*)&qp[(size_t)(s0 + r) * ND + d4];
        int col = (r + d4) & 63;
        Qt[d4 + 0][col] = a.x;
        Qt[d4 + 1][col] = a.y;
        Qt[d4 + 2][col] = a.z;
        Qt[d4 + 3][col] = a.w;
    }

    float o[4][8];
    float mrow[4], lrow[4];
#pragma unroll
    for (int i = 0; i < 4; i++) {
        mrow[i] = -1e30f;
        lrow[i] = 0.f;
#pragma unroll
        for (int j = 0; j < 8; j++) o[i][j] = 0.f;
    }

    for (int t0 = 0; t0 < NS; t0 += 64) {
        __syncthreads();
#pragma unroll
        for (int rep = 0; rep < 8; rep++) {
            int idx = tid + rep * 128;
            int t  = idx >> 4;
            int d4 = (idx & 15) << 2;
            float4 a = *(const float4*)&kp[(size_t)(t0 + t) * ND + d4];
            int col = (t + d4) & 63;
            KPs[d4 + 0][col] = a.x;
            KPs[d4 + 1][col] = a.y;
            KPs[d4 + 2][col] = a.z;
            KPs[d4 + 3][col] = a.w;
            *(float4*)&Vs[t][d4] =
                *(const float4*)&vp[(size_t)(t0 + t) * ND + d4];
        }
        __syncthreads();

        float sc[4][8];
#pragma unroll
        for (int i = 0; i < 4; i++)
#pragma unroll
            for (int j = 0; j < 8; j++) sc[i][j] = 0.f;

#pragma unroll 16
        for (int d = 0; d < 64; d++) {
            const int rot = d & ~3;
            float av[4], bv[8];
            *(float4*)&av[0] = *(const float4*)&Qt[d][(ty4 + rot) & 63];
            *(float4*)&bv[0] = *(const float4*)&KPs[d][(tx4 + rot) & 63];
            *(float4*)&bv[4] = *(const float4*)&KPs[d][(tx4 + 32 + rot) & 63];
#pragma unroll
            for (int i = 0; i < 4; i++)
#pragma unroll
                for (int j = 0; j < 8; j++)
                    sc[i][j] += av[i] * bv[j];
        }

#pragma unroll
        for (int i = 0; i < 4; i++) {
            const float* bp = &bias[(size_t)(s0 + ty4 + i) * NS + t0];
            float4 b0 = *(const float4*)&bp[tx4];
            float4 b1 = *(const float4*)&bp[tx4 + 32];
            sc[i][0] = sc[i][0] * 0.125f + b0.x;
            sc[i][1] = sc[i][1] * 0.125f + b0.y;
            sc[i][2] = sc[i][2] * 0.125f + b0.z;
            sc[i][3] = sc[i][3] * 0.125f + b0.w;
            sc[i][4] = sc[i][4] * 0.125f + b1.x;
            sc[i][5] = sc[i][5] * 0.125f + b1.y;
            sc[i][6] = sc[i][6] * 0.125f + b1.z;
            sc[i][7] = sc[i][7] * 0.125f + b1.w;
        }

        float alpha[4];
#pragma unroll
        for (int i = 0; i < 4; i++) {
            float mt = sc[i][0];
#pragma unroll
            for (int j = 1; j < 8; j++) mt = fmaxf(mt, sc[i][j]);
#pragma unroll
            for (int off = 1; off < 8; off <<= 1)
                mt = fmaxf(mt, __shfl_xor_sync(0xffffffffu, mt, off));
            float mnew = fmaxf(mrow[i], mt);
            alpha[i] = __expf(mrow[i] - mnew);
            mrow[i] = mnew;
            float rs = 0.f;
#pragma unroll
            for (int j = 0; j < 8; j++) {
                sc[i][j] = __expf(sc[i][j] - mnew);
                rs += sc[i][j];
            }
#pragma unroll
            for (int off = 1; off < 8; off <<= 1)
                rs += __shfl_xor_sync(0xffffffffu, rs, off);
            lrow[i] = lrow[i] * alpha[i] + rs;
        }

        __syncthreads();
#pragma unroll
        for (int i = 0; i < 4; i++) {
            float4 p0 = make_float4(sc[i][0], sc[i][1], sc[i][2], sc[i][3]);
            float4 p1 = make_float4(sc[i][4], sc[i][5], sc[i][6], sc[i][7]);
            *(float4*)&KPs[ty4 + i][tx4] = p0;
            *(float4*)&KPs[ty4 + i][tx4 + 32] = p1;
        }
        __syncthreads();

#pragma unroll
        for (int i = 0; i < 4; i++)
#pragma unroll
            for (int j = 0; j < 8; j++) o[i][j] *= alpha[i];

#pragma unroll
        for (int t4 = 0; t4 < 64; t4 += 4) {
            float a[4][4];
#pragma unroll
            for (int i = 0; i < 4; i++)
                *(float4*)&a[i][0] = *(const float4*)&KPs[ty4 + i][t4];
#pragma unroll
            for (int c = 0; c < 4; c++) {
                float vv[8];
                *(float4*)&vv[0] = *(const float4*)&Vs[t4 + c][tx4];
                *(float4*)&vv[4] = *(const float4*)&Vs[t4 + c][tx4 + 32];
#pragma unroll
                for (int i = 0; i < 4; i++)
#pragma unroll
                    for (int j = 0; j < 8; j++)
                        o[i][j] += a[i][c] * vv[j];
            }
        }
    }

    const int b = bh >> 4;
    const int h = bh & 15;
#pragma unroll
    for (int i = 0; i < 4; i++) {
        float inv = 1.f / lrow[i];
        size_t base = ((size_t)b * NS + s0 + ty4 + i) * NE + h * ND;
#pragma unroll
        for (int half = 0; half < 2; half++) {
            int j0 = half * 4;
            size_t adr = base + tx4 + half * 32;
            float x0 = o[i][j0 + 0] * inv, x1 = o[i][j0 + 1] * inv;
            float x2 = o[i][j0 + 2] * inv, x3 = o[i][j0 + 3] * inv;
            *(float4*)&ctx[adr] = make_float4(x0, x1, x2, x3);
            __nv_bfloat16 h0 = __float2bfloat16(x0), h1 = __float2bfloat16(x1);
            __nv_bfloat16 h2 = __float2bfloat16(x2), h3 = __float2bfloat16(x3);
            *(__nv_bfloat162*)&ctx_h[adr]     = __nv_bfloat162(h0, h1);
            *(__nv_bfloat162*)&ctx_h[adr + 2] = __nv_bfloat162(h2, h3);
            __nv_bfloat16 l0 = __float2bfloat16(x0 - __bfloat162float(h0));
            __nv_bfloat16 l1 = __float2bfloat16(x1 - __bfloat162float(h1));
            __nv_bfloat16 l2 = __float2bfloat16(x2 - __bfloat162float(h2));
            __nv_bfloat16 l3 = __float2bfloat16(x3 - __bfloat162float(h3));
            *(__nv_bfloat162*)&ctx_l[adr]     = __nv_bfloat162(l0, l1);
            *(__nv_bfloat162*)&ctx_l[adr + 2] = __nv_bfloat162(l2, l3);
        }
    }
}

// ---------------------------------------------------------------------------

extern "C" void kernel_launch(void* const* d_in, const int* in_sizes, int n_in,
                              void* d_out, int out_size)
{
    const float* query = (const float*)d_in[0];
    const float* key_  = (const float*)d_in[1];
    const float* value = (const float*)d_in[2];
    const float* abias = (const float*)d_in[3];
    const float* Wq = (const float*)d_in[4];
    const float* bq = (const float*)d_in[5];
    const float* Wk = (const float*)d_in[6];
    const float* bk = (const float*)d_in[7];
    const float* Wv = (const float*)d_in[8];
    const float* bv = (const float*)d_in[9];
    const float* Wo = (const float*)d_in[10];
    const float* bo = (const float*)d_in[11];
    float* out = (float*)d_out;

    float *qp, *kp, *vp, *cp;
    __nv_bfloat16 *ah, *al, *wth, *wtl;
    cudaGetSymbolAddress((void**)&qp, g_q);
    cudaGetSymbolAddress((void**)&kp, g_k);
    cudaGetSymbolAddress((void**)&vp, g_v);
    cudaGetSymbolAddress((void**)&cp, g_ctx);
    cudaGetSymbolAddress((void**)&ah, g_ah);
    cudaGetSymbolAddress((void**)&al, g_al);
    cudaGetSymbolAddress((void**)&wth, g_wth);
    cudaGetSymbolAddress((void**)&wtl, g_wtl);

    cudaFuncSetAttribute(gemm_mma_kernel,
                         cudaFuncAttributeMaxDynamicSharedMemorySize,
                         GEMM_SMEM_BYTES);

    probe_kernel<<<1, 1>>>();

    const int nsplit = NB * NS * NE / 4 / 256;
    dim3 gw(16, 1, 16);
    dim3 ggemm(64, 4);
    dim3 gproj(64, 16);

    // Q projection
    transpose_split_kernel<<<gw, 256>>>(Wq, wth, wtl, ND);
    split_kernel<<<nsplit, 256>>>(query, ah, al);
    gemm_mma_kernel<<<ggemm, 128, GEMM_SMEM_BYTES>>>(ah, al, wth, wtl, bq, qp, 0);
    proj_kernel<<<gproj, 256>>>(query, Wq, bq, qp);
    // K projection
    transpose_split_kernel<<<gw, 256>>>(Wk, wth, wtl, ND);
    split_kernel<<<nsplit, 256>>>(key_, ah, al);
    gemm_mma_kernel<<<ggemm, 128, GEMM_SMEM_BYTES>>>(ah, al, wth, wtl, bk, kp, 0);
    proj_kernel<<<gproj, 256>>>(key_, Wk, bk, kp);
    // V projection
    transpose_split_kernel<<<gw, 256>>>(Wv, wth, wtl, ND);
    split_kernel<<<nsplit, 256>>>(value, ah, al);
    gemm_mma_kernel<<<ggemm, 128, GEMM_SMEM_BYTES>>>(ah, al, wth, wtl, bv, vp, 0);
    proj_kernel<<<gproj, 256>>>(value, Wv, bv, vp);

    // attention (fp32) -> ctx fp32 + bf16 hi/lo
    dim3 gattn(32, 64);
    attn_kernel<<<gattn, 128>>>(qp, kp, vp, abias, cp, ah, al);

    // output projection
    dim3 gwo(16, 16, 1);
    transpose_split_kernel<<<gwo, 256>>>(Wo, wth, wtl, NE);
    gemm_mma_kernel<<<ggemm, 128, GEMM_SMEM_BYTES>>>(ah, al, wth, wtl, bo, out, 1);
    outproj_kernel<<<dim3(64, 16), 256>>>(cp, Wo, bo, out);
}

// round 5
// speedup vs baseline: 2.7238x; 1.9460x over previous
#include <cuda_runtime.h>
#include <cuda_bf16.h>
#include <cstdint>

#define NB 4
#define NS 2048
#define NE 1024
#define NH 16
#define ND 64

#if defined(__CUDA_ARCH__) && (defined(__CUDA_ARCH_FEAT_SM103_ALL) || \
    defined(__CUDA_ARCH_SPECIFIC__))
#define HAS_TCGEN05 1
#else
#define HAS_TCGEN05 0
#endif

// ---------------------------------------------------------------------------
// Device globals (scratch)
// ---------------------------------------------------------------------------
__device__ __align__(256) float g_v[NB * NH * NS * ND];          // v fp32 per-head
__device__ __align__(256) __nv_bfloat16 g_qh[NB * NH * NS * ND];
__device__ __align__(256) __nv_bfloat16 g_ql[NB * NH * NS * ND];
__device__ __align__(256) __nv_bfloat16 g_kh[NB * NH * NS * ND];
__device__ __align__(256) __nv_bfloat16 g_kl[NB * NH * NS * ND];
__device__ __align__(256) __nv_bfloat16 g_vth[NB * NH * ND * NS]; // V^T [bh][d][s]
__device__ __align__(256) __nv_bfloat16 g_vtl[NB * NH * ND * NS];
__device__ __align__(256) __nv_bfloat16 g_ah[NB * NS * NE];       // activations / ctx
__device__ __align__(256) __nv_bfloat16 g_al[NB * NS * NE];
__device__ __align__(256) __nv_bfloat16 g_wth[NE * NE];
__device__ __align__(256) __nv_bfloat16 g_wtl[NE * NE];

// ---------------------------------------------------------------------------
// PTX helpers
// ---------------------------------------------------------------------------
__device__ __forceinline__ uint32_t smem_u32(const void* p) {
    uint32_t a;
    asm("{ .reg .u64 t; cvta.to.shared.u64 t, %1; cvt.u32.u64 %0, t; }"
        : "=r"(a) : "l"(p));
    return a;
}
__device__ __forceinline__ uint32_t elect_one() {
    uint32_t pred;
    asm volatile("{ .reg .pred p; elect.sync _|p, 0xFFFFFFFF; selp.b32 %0,1,0,p; }"
                 : "=r"(pred));
    return pred;
}
#define MBARRIER_INIT(addr, cnt) \
    asm volatile("mbarrier.init.shared.b64 [%0], %1;" :: "r"(addr), "r"(cnt) : "memory")
#define MBARRIER_WAIT_PARITY(addr, par) do {                                   \
    uint32_t _m = (addr), _p = (par), _d;                                      \
    asm volatile("{ .reg .pred p; mbarrier.try_wait.parity.acquire.cta.shared::cta.b64 p, [%1], %2; selp.b32 %0,1,0,p; }" \
        : "=r"(_d) : "r"(_m), "r"(_p) : "memory");                             \
    if (!_d) {                                                                 \
        asm volatile("{ .reg .pred P1; WL_%=: mbarrier.try_wait.parity.acquire.cta.shared::cta.b64 P1, [%0], %1, 0x989680; @P1 bra.uni WD_%=; bra.uni WL_%=; WD_%=: }" \
            :: "r"(_m), "r"(_p) : "memory");                                   \
    } } while (0)
#define TCGEN05_ALLOC(saddr, ncols) \
    asm volatile("tcgen05.alloc.cta_group::1.sync.aligned.shared::cta.b32 [%0], %1;" \
        :: "r"((uint32_t)(saddr)), "r"((uint32_t)(ncols)) : "memory")
#define TCGEN05_DEALLOC(tmem, ncols) \
    asm volatile("tcgen05.dealloc.cta_group::1.sync.aligned.b32 %0, %1;" \
        :: "r"(tmem), "r"((uint32_t)(ncols)))
#define TCGEN05_COMMIT(mbar) \
    asm volatile("tcgen05.commit.cta_group::1.mbarrier::arrive::one.shared::cluster.b64 [%0];" \
        :: "r"((uint32_t)(mbar)) : "memory")
#define TCGEN05_WAIT_LD() asm volatile("tcgen05.wait::ld.sync.aligned;" ::: "memory")
#define TCGEN05_FENCE_AFTER() asm volatile("tcgen05.fence::after_thread_sync;" ::: "memory")
#define TCGEN05_FENCE_BEFORE() asm volatile("tcgen05.fence::before_thread_sync;" ::: "memory")
#define FENCE_ASYNC() asm volatile("fence.proxy.async.shared::cta;" ::: "memory")

#define TCGEN05_LD_X32(r, ta)                                                  \
    asm volatile("tcgen05.ld.sync.aligned.32x32b.x32.b32 "                     \
        "{%0,%1,%2,%3,%4,%5,%6,%7,%8,%9,%10,%11,%12,%13,%14,%15,"             \
        "%16,%17,%18,%19,%20,%21,%22,%23,%24,%25,%26,%27,%28,%29,%30,%31}, [%32];" \
        : "=r"((r)[0]),"=r"((r)[1]),"=r"((r)[2]),"=r"((r)[3]),                 \
          "=r"((r)[4]),"=r"((r)[5]),"=r"((r)[6]),"=r"((r)[7]),                 \
          "=r"((r)[8]),"=r"((r)[9]),"=r"((r)[10]),"=r"((r)[11]),               \
          "=r"((r)[12]),"=r"((r)[13]),"=r"((r)[14]),"=r"((r)[15]),             \
          "=r"((r)[16]),"=r"((r)[17]),"=r"((r)[18]),"=r"((r)[19]),             \
          "=r"((r)[20]),"=r"((r)[21]),"=r"((r)[22]),"=r"((r)[23]),             \
          "=r"((r)[24]),"=r"((r)[25]),"=r"((r)[26]),"=r"((r)[27]),             \
          "=r"((r)[28]),"=r"((r)[29]),"=r"((r)[30]),"=r"((r)[31])              \
        : "r"(ta))

#if HAS_TCGEN05
__device__ __forceinline__ uint64_t make_desc(uint32_t addr) {
    const uint64_t base = (uint64_t(2) << 61) | (uint64_t(1) << 46) |
                          (uint64_t(64) << 32) | (uint64_t(1) << 16);
    return base | ((uint64_t)(addr >> 4) & 0x3FFF);
}
__device__ __forceinline__ void mma_f16_ss(uint32_t d, uint64_t a, uint64_t b,
                                           uint32_t idesc, uint32_t en) {
    asm volatile(
        "{ .reg .pred p; setp.ne.u32 p, %4, 0;\n\t"
        "tcgen05.mma.cta_group::1.kind::f16 [%0], %1, %2, %3, {%5,%5,%5,%5}, p; }"
        :: "r"(d), "l"(a), "l"(b), "r"(idesc), "r"(en), "r"(0u) : "memory");
}
#endif

__device__ __forceinline__ uint32_t pack_bf2(float a, float b) {
    __nv_bfloat162 t = __floats2bfloat162_rn(a, b);
    return *(uint32_t*)&t;
}

// ---------------------------------------------------------------------------
// GEMM (tcgen05): out[8192,1024] = (Ah+Al) * (Bh+Bl)^T + bias
// 256 threads, 2-stage smem, register-prefetch of next chunk.
// mode 0: bf16 hi/lo per-head (q,k). mode 1: fp32 flat. mode 2: fp32 per-head.
// ---------------------------------------------------------------------------
#define GEMM_MT 128
#define GEMM_NT 256
#define GEMM_IDESC ((1u<<4)|(1u<<7)|(1u<<10)|((GEMM_NT/8)<<17)|((GEMM_MT/16)<<24))
#define GEMM_BUF_BYTES 98304
#define GEMM_SMEM_BYTES (1024 + 2 * GEMM_BUF_BYTES)

#if HAS_TCGEN05
template <int NIT>
__device__ __forceinline__ void ld_regs(const __nv_bfloat16* __restrict__ g,
                                        int row0, uint4* r, int tid) {
#pragma unroll
    for (int it = 0; it < NIT; it++) {
        int idx = tid + it * 256;
        int row = idx >> 3, q = idx & 7;
        r[it] = *((const uint4*)(g + (size_t)(row0 + row) * NE) + q);
    }
}
template <int NIT>
__device__ __forceinline__ void st_regs(char* s, const uint4* r, int tid) {
#pragma unroll
    for (int it = 0; it < NIT; it++) {
        int idx = tid + it * 256;
        int row = idx >> 3, q = idx & 7;
        uint32_t off = (uint32_t)(row * 128 + q * 16);
        off ^= (off >> 3) & 0x70;
        *(uint4*)(s + off) = r[it];
    }
}
#endif

__global__ __launch_bounds__(256) void gemm_mma_kernel(
    const __nv_bfloat16* __restrict__ Ah, const __nv_bfloat16* __restrict__ Al,
    const __nv_bfloat16* __restrict__ Bh, const __nv_bfloat16* __restrict__ Bl,
    const float* __restrict__ bias, float* __restrict__ outF,
    __nv_bfloat16* __restrict__ outH, __nv_bfloat16* __restrict__ outL,
    int mode)
{
#if HAS_TCGEN05
    extern __shared__ __align__(1024) char smem[];
    const uint32_t sb = smem_u32(smem);
    const int tid = threadIdx.x;
    const int wid = tid >> 5, lid = tid & 31;
    const int m0 = blockIdx.x * GEMM_MT;
    const int n0 = blockIdx.y * GEMM_NT;

    if (wid == 0) TCGEN05_ALLOC(sb, 512);
    if (tid == 0) { MBARRIER_INIT(sb + 16, 1); MBARRIER_INIT(sb + 24, 1); }
    __syncthreads();
    uint32_t tmem;
    asm volatile("ld.shared.b32 %0, [%1];" : "=r"(tmem) : "r"(sb));

    uint4 rAh[4], rAl[4], rBh[8], rBl[8];
    ld_regs<4>(Ah, m0, rAh, tid);
    ld_regs<4>(Al, m0, rAl, tid);
    ld_regs<8>(Bh, n0, rBh, tid);
    ld_regs<8>(Bl, n0, rBl, tid);

    int ph0 = 0, ph1 = 0;
    for (int c = 0; c < 16; c++) {
        const int buf = c & 1;
        char* bs = smem + 1024 + buf * GEMM_BUF_BYTES;
        if (c >= 2) {
            if (buf == 0) { MBARRIER_WAIT_PARITY(sb + 16, ph0); ph0 ^= 1; }
            else          { MBARRIER_WAIT_PARITY(sb + 24, ph1); ph1 ^= 1; }
        }
        st_regs<4>(bs, rAh, tid);
        st_regs<4>(bs + 16384, rAl, tid);
        st_regs<8>(bs + 32768, rBh, tid);
        st_regs<8>(bs + 65536, rBl, tid);
        if (c < 15) {
            const int k1 = (c + 1) * 64;
            ld_regs<4>(Ah + k1, m0, rAh, tid);
            ld_regs<4>(Al + k1, m0, rAl, tid);
            ld_regs<8>(Bh + k1, n0, rBh, tid);
            ld_regs<8>(Bl + k1, n0, rBl, tid);
        }
        __syncthreads();

        if (wid == 0 && elect_one()) {
            FENCE_ASYNC();
            const uint32_t ba = sb + 1024 + buf * GEMM_BUF_BYTES;
            uint64_t dah = make_desc(ba);
            uint64_t dal = make_desc(ba + 16384);
            uint64_t dbh = make_desc(ba + 32768);
            uint64_t dbl = make_desc(ba + 65536);
#pragma unroll
            for (int s = 0; s < 4; s++) {
                uint64_t o2 = 2u * s;
                mma_f16_ss(tmem, dah + o2, dbh + o2, GEMM_IDESC,
                           (c > 0 || s > 0) ? 1u : 0u);
                mma_f16_ss(tmem, dal + o2, dbh + o2, GEMM_IDESC, 1u);
                mma_f16_ss(tmem, dah + o2, dbl + o2, GEMM_IDESC, 1u);
            }
            TCGEN05_COMMIT(sb + 16 + buf * 8);
        }
    }
    MBARRIER_WAIT_PARITY(sb + 16, ph0);
    MBARRIER_WAIT_PARITY(sb + 24, ph1);
    TCGEN05_FENCE_AFTER();

    // Epilogue: warp w handles rows m0+32*(w&3)+lane, col-half (w>>2)*128.
    const int m = m0 + 32 * (wid & 3) + lid;
    const int b = m >> 11, s_ = m & (NS - 1);
    const int chalf = (wid >> 2) * 128;
#pragma unroll
    for (int i = 0; i < 4; i++) {
        uint32_t r[32];
        TCGEN05_LD_X32(r, tmem + chalf + i * 32);
        TCGEN05_WAIT_LD();
        const int nbase = n0 + chalf + i * 32;
        float vals[32];
        const float4* bp = (const float4*)(bias + nbase);
#pragma unroll
        for (int j4 = 0; j4 < 8; j4++) {
            float4 bb = bp[j4];
            vals[j4 * 4 + 0] = __uint_as_float(r[j4 * 4 + 0]) + bb.x;
            vals[j4 * 4 + 1] = __uint_as_float(r[j4 * 4 + 1]) + bb.y;
            vals[j4 * 4 + 2] = __uint_as_float(r[j4 * 4 + 2]) + bb.z;
            vals[j4 * 4 + 3] = __uint_as_float(r[j4 * 4 + 3]) + bb.w;
        }
        if (mode == 1) {
            float* dst = outF + ((size_t)m * NE + nbase);
#pragma unroll
            for (int j = 0; j < 32; j += 4)
                *(float4*)(dst + j) = make_float4(vals[j], vals[j+1], vals[j+2], vals[j+3]);
        } else {
            const int h = nbase >> 6, d0 = nbase & 63;
            const size_t base = ((size_t)(b * NH + h) * NS + s_) * ND + d0;
            if (mode == 2) {
                float* dst = outF + base;
#pragma unroll
                for (int j = 0; j < 32; j += 4)
                    *(float4*)(dst + j) = make_float4(vals[j], vals[j+1], vals[j+2], vals[j+3]);
            } else {
#pragma unroll
                for (int c8 = 0; c8 < 4; c8++) {
                    uint4 wh, wl;
                    uint32_t* ph_ = &wh.x;
                    uint32_t* pl_ = &wl.x;
#pragma unroll
                    for (int p2 = 0; p2 < 4; p2++) {
                        float a = vals[c8 * 8 + p2 * 2];
                        float bv = vals[c8 * 8 + p2 * 2 + 1];
                        __nv_bfloat16 ha = __float2bfloat16(a);
                        __nv_bfloat16 hb = __float2bfloat16(bv);
                        ph_[p2] = pack_bf2(a, bv);
                        pl_[p2] = pack_bf2(a - __bfloat162float(ha),
                                           bv - __bfloat162float(hb));
                    }
                    *(uint4*)(outH + base + c8 * 8) = wh;
                    *(uint4*)(outL + base + c8 * 8) = wl;
                }
            }
        }
    }

    __syncthreads();
    if (wid == 0) TCGEN05_DEALLOC(tmem, 512);
#else
    (void)Ah;(void)Al;(void)Bh;(void)Bl;(void)bias;(void)outF;(void)outH;(void)outL;(void)mode;
#endif
}

// ---------------------------------------------------------------------------
// tcgen05 flash attention, max-free softmax.
// Per CTA: 128 q-rows of one (b,h); 32 kv tiles of 64. 128 threads.
// ---------------------------------------------------------------------------
#define AT_Q   1024
#define AT_QL  (AT_Q + 16384)
#define AT_STG (AT_QL + 16384)          // 2 stages x 32KB: Kh,Kl,Vh,Vl (8KB each)
#define AT_PH  (AT_STG + 2 * 32768)
#define AT_PL  (AT_PH + 16384)
#define AT_SMEM_BYTES (AT_PL + 16384)
#define AT_IDESC ((1u<<4)|(1u<<7)|(1u<<10)|((64/8)<<17)|((128/16)<<24))

__global__ __launch_bounds__(128) void attn_mma_kernel(
    const __nv_bfloat16* __restrict__ qh, const __nv_bfloat16* __restrict__ ql,
    const __nv_bfloat16* __restrict__ kh, const __nv_bfloat16* __restrict__ kl,
    const __nv_bfloat16* __restrict__ vth, const __nv_bfloat16* __restrict__ vtl,
    const float* __restrict__ bias,
    __nv_bfloat16* __restrict__ ctx_h, __nv_bfloat16* __restrict__ ctx_l)
{
#if HAS_TCGEN05
    extern __shared__ __align__(1024) char smem[];
    const uint32_t sb = smem_u32(smem);
    const int tid = threadIdx.x;
    const int wid = tid >> 5, lid = tid & 31;
    const int s0 = blockIdx.x * 128;
    const int bh = blockIdx.y;

    const __nv_bfloat16* qhp = qh + ((size_t)bh * NS + s0) * ND;
    const __nv_bfloat16* qlp = ql + ((size_t)bh * NS + s0) * ND;
    const __nv_bfloat16* khp = kh + (size_t)bh * NS * ND;
    const __nv_bfloat16* klp = kl + (size_t)bh * NS * ND;
    const __nv_bfloat16* vhp = vth + (size_t)bh * ND * NS;
    const __nv_bfloat16* vlp = vtl + (size_t)bh * ND * NS;

    if (wid == 0) TCGEN05_ALLOC(sb, 128);
    if (tid == 0) MBARRIER_INIT(sb + 16, 1);
    __syncthreads();
    uint32_t tmem;
    asm volatile("ld.shared.b32 %0, [%1];" : "=r"(tmem) : "r"(sb));

    // Q tiles (hi/lo), swizzled
#pragma unroll
    for (int it = 0; it < 8; it++) {
        int idx = tid + it * 128;
        int row = idx >> 3, q = idx & 7;
        uint32_t off = (uint32_t)(row * 128 + q * 16);
        off ^= (off >> 3) & 0x70;
        *(uint4*)(smem + AT_Q + off)  = *((const uint4*)(qhp + (size_t)row * ND) + q);
        *(uint4*)(smem + AT_QL + off) = *((const uint4*)(qlp + (size_t)row * ND) + q);
    }

    // KV tile loader (64 rows x 128B each of Kh,Kl and 64 d-rows of Vh,Vl)
    auto ld_kv = [&](int t, int stg) {
        char* ks = smem + AT_STG + stg * 32768;
        const __nv_bfloat16* kh_t = khp + (size_t)t * 64 * ND;
        const __nv_bfloat16* kl_t = klp + (size_t)t * 64 * ND;
        const __nv_bfloat16* vh_t = vhp + (size_t)t * 64;   // [d][s] rows stride NS
        const __nv_bfloat16* vl_t = vlp + (size_t)t * 64;
#pragma unroll
        for (int it = 0; it < 4; it++) {
            int idx = tid + it * 128;
            int row = idx >> 3, q = idx & 7;
            uint32_t off = (uint32_t)(row * 128 + q * 16);
            off ^= (off >> 3) & 0x70;
            *(uint4*)(ks + off)         = *((const uint4*)(kh_t + (size_t)row * ND) + q);
            *(uint4*)(ks + 8192 + off)  = *((const uint4*)(kl_t + (size_t)row * ND) + q);
            *(uint4*)(ks + 16384 + off) = *((const uint4*)(vh_t + (size_t)row * NS) + q);
            *(uint4*)(ks + 24576 + off) = *((const uint4*)(vl_t + (size_t)row * NS) + q);
        }
    };

    const uint64_t dq_h = make_desc(sb + AT_Q);
    const uint64_t dq_l = make_desc(sb + AT_QL);
    const uint64_t dp_h = make_desc(sb + AT_PH);
    const uint64_t dp_l = make_desc(sb + AT_PL);

    ld_kv(0, 0);
    __syncthreads();
    if (wid == 0 && elect_one()) {
        FENCE_ASYNC();
        const uint32_t ks = sb + AT_STG;
        uint64_t dk_h = make_desc(ks), dk_l = make_desc(ks + 8192);
#pragma unroll
        for (int s4 = 0; s4 < 4; s4++) {
            uint64_t o2 = 2u * s4;
            mma_f16_ss(tmem, dq_h + o2, dk_h + o2, AT_IDESC, s4 > 0);
            mma_f16_ss(tmem, dq_l + o2, dk_h + o2, AT_IDESC, 1u);
            mma_f16_ss(tmem, dq_h + o2, dk_l + o2, AT_IDESC, 1u);
        }
        TCGEN05_COMMIT(sb + 16);
    }

    const int row = 32 * wid + lid;
    const float* brow = bias + (size_t)(s0 + row) * NS;
    float lsum = 0.f;
    int ph = 0;

    for (int t = 0; t < 32; t++) {
        MBARRIER_WAIT_PARITY(sb + 16, ph);
        ph ^= 1;
        if (t + 1 < 32) ld_kv(t + 1, (t + 1) & 1);

        // bias prefetch for this tile (own row, 64 floats)
        float4 bb[16];
        const float4* bp = (const float4*)(brow + t * 64);
#pragma unroll
        for (int i = 0; i < 16; i++) bb[i] = bp[i];

        TCGEN05_FENCE_AFTER();
#pragma unroll
        for (int hf = 0; hf < 2; hf++) {
            uint32_t r[32];
            TCGEN05_LD_X32(r, tmem + hf * 32);
            TCGEN05_WAIT_LD();
            float p[32];
#pragma unroll
            for (int j4 = 0; j4 < 8; j4++) {
                float4 b4 = bb[hf * 8 + j4];
                p[j4*4+0] = __expf(fmaf(__uint_as_float(r[j4*4+0]), 0.125f, b4.x));
                p[j4*4+1] = __expf(fmaf(__uint_as_float(r[j4*4+1]), 0.125f, b4.y));
                p[j4*4+2] = __expf(fmaf(__uint_as_float(r[j4*4+2]), 0.125f, b4.z));
                p[j4*4+3] = __expf(fmaf(__uint_as_float(r[j4*4+3]), 0.125f, b4.w));
                lsum += p[j4*4+0] + p[j4*4+1] + p[j4*4+2] + p[j4*4+3];
            }
#pragma unroll
            for (int c4 = 0; c4 < 4; c4++) {
                uint4 wh, wl;
                uint32_t* phh = &wh.x;
                uint32_t* pll = &wl.x;
#pragma unroll
                for (int p2 = 0; p2 < 4; p2++) {
                    float a = p[c4 * 8 + p2 * 2];
                    float c = p[c4 * 8 + p2 * 2 + 1];
                    __nv_bfloat16 ha = __float2bfloat16(a);
                    __nv_bfloat16 hc = __float2bfloat16(c);
                    phh[p2] = pack_bf2(a, c);
                    pll[p2] = pack_bf2(a - __bfloat162float(ha),
                                       c - __bfloat162float(hc));
                }
                uint32_t off = (uint32_t)(row * 128 + hf * 64 + c4 * 16);
                off ^= (off >> 3) & 0x70;
                *(uint4*)(smem + AT_PH + off) = wh;
                *(uint4*)(smem + AT_PL + off) = wl;
            }
        }
        TCGEN05_FENCE_BEFORE();
        __syncthreads();

        if (wid == 0 && elect_one()) {
            FENCE_ASYNC();
            const uint32_t ks = sb + AT_STG + (t & 1) * 32768;
            uint64_t dv_h = make_desc(ks + 16384), dv_l = make_desc(ks + 24576);
#pragma unroll
            for (int s4 = 0; s4 < 4; s4++) {
                uint64_t o2 = 2u * s4;
                mma_f16_ss(tmem + 64, dp_h + o2, dv_h + o2, AT_IDESC,
                           (t > 0 || s4 > 0) ? 1u : 0u);
                mma_f16_ss(tmem + 64, dp_l + o2, dv_h + o2, AT_IDESC, 1u);
                mma_f16_ss(tmem + 64, dp_h + o2, dv_l + o2, AT_IDESC, 1u);
            }
            if (t + 1 < 32) {
                const uint32_t ks2 = sb + AT_STG + ((t + 1) & 1) * 32768;
                uint64_t dk_h = make_desc(ks2), dk_l = make_desc(ks2 + 8192);
#pragma unroll
                for (int s4 = 0; s4 < 4; s4++) {
                    uint64_t o2 = 2u * s4;
                    mma_f16_ss(tmem, dq_h + o2, dk_h + o2, AT_IDESC, s4 > 0);
                    mma_f16_ss(tmem, dq_l + o2, dk_h + o2, AT_IDESC, 1u);
                    mma_f16_ss(tmem, dq_h + o2, dk_l + o2, AT_IDESC, 1u);
                }
            }
            TCGEN05_COMMIT(sb + 16);
        }
    }
    MBARRIER_WAIT_PARITY(sb + 16, ph);
    TCGEN05_FENCE_AFTER();

    // epilogue: O / lsum -> ctx bf16 hi/lo at [b][s][h*64+d]
    const float inv = 1.f / lsum;
    const int b = bh >> 4, h = bh & 15;
    const size_t obase = ((size_t)b * NS + s0 + row) * NE + h * ND;
#pragma unroll
    for (int hf = 0; hf < 2; hf++) {
        uint32_t r[32];
        TCGEN05_LD_X32(r, tmem + 64 + hf * 32);
        TCGEN05_WAIT_LD();
#pragma unroll
        for (int c8 = 0; c8 < 4; c8++) {
            uint4 wh, wl;
            uint32_t* phh = &wh.x;
            uint32_t* pll = &wl.x;
#pragma unroll
            for (int p2 = 0; p2 < 4; p2++) {
                float a = __uint_as_float(r[c8 * 8 + p2 * 2]) * inv;
                float c = __uint_as_float(r[c8 * 8 + p2 * 2 + 1]) * inv;
                __nv_bfloat16 ha = __float2bfloat16(a);
                __nv_bfloat16 hc = __float2bfloat16(c);
                phh[p2] = pack_bf2(a, c);
                pll[p2] = pack_bf2(a - __bfloat162float(ha),
                                   c - __bfloat162float(hc));
            }
            *(uint4*)(ctx_h + obase + hf * 32 + c8 * 8) = wh;
            *(uint4*)(ctx_l + obase + hf * 32 + c8 * 8) = wl;
        }
    }
    TCGEN05_FENCE_BEFORE();
    __syncthreads();
    if (wid == 0) TCGEN05_DEALLOC(tmem, 128);
#else
    (void)qh;(void)ql;(void)kh;(void)kl;(void)vth;(void)vtl;(void)bias;(void)ctx_h;(void)ctx_l;
#endif
}

// ---------------------------------------------------------------------------
// fp32 -> bf16 hi/lo split (elementwise)
// ---------------------------------------------------------------------------
__global__ __launch_bounds__(256) void split_kernel(
    const float* __restrict__ x, __nv_bfloat16* __restrict__ hh,
    __nv_bfloat16* __restrict__ ll)
{
    int i = blockIdx.x * 256 + threadIdx.x;
    float4 v = ((const float4*)x)[i];
    __nv_bfloat16 h0 = __float2bfloat16(v.x);
    __nv_bfloat16 h1 = __float2bfloat16(v.y);
    __nv_bfloat16 h2 = __float2bfloat16(v.z);
    __nv_bfloat16 h3 = __float2bfloat16(v.w);
    ((uint32_t*)hh)[2 * i]     = pack_bf2(v.x, v.y);
    ((uint32_t*)hh)[2 * i + 1] = pack_bf2(v.z, v.w);
    ((uint32_t*)ll)[2 * i]     = pack_bf2(v.x - __bfloat162float(h0),
                                          v.y - __bfloat162float(h1));
    ((uint32_t*)ll)[2 * i + 1] = pack_bf2(v.z - __bfloat162float(h2),
                                          v.w - __bfloat162float(h3));
}

// ---------------------------------------------------------------------------
// transpose + split: in[z][R][C] fp32 -> out[(z*C + c)][R] bf16 hi/lo
// grid (R/64, C/64, Z), 256 threads.
// ---------------------------------------------------------------------------
__global__ __launch_bounds__(256) void transpose_split_kernel(
    const float* __restrict__ in, __nv_bfloat16* __restrict__ oh,
    __nv_bfloat16* __restrict__ ol, int C, int R)
{
    __shared__ float t[64][65];
    const float* inz = in + (size_t)blockIdx.z * R * C;
    const int r0 = blockIdx.x * 64, c0 = blockIdx.y * 64;
    const int tid = threadIdx.x;
#pragma unroll
    for (int it = 0; it < 16; it++) {
        int idx = tid + it * 256;
        int rr = idx >> 6, cc = idx & 63;
        t[rr][cc] = inz[(size_t)(r0 + rr) * C + c0 + cc];
    }
    __syncthreads();
#pragma unroll
    for (int it = 0; it < 16; it++) {
        int idx = tid + it * 256;
        int cc = idx >> 6, rr = idx & 63;
        float x = t[rr][cc];
        __nv_bfloat16 hi = __float2bfloat16(x);
        size_t o = (size_t)(blockIdx.z * C + c0 + cc) * R + r0 + rr;
        oh[o] = hi;
        ol[o] = __float2bfloat16(x - __bfloat162float(hi));
    }
}

// ---------------------------------------------------------------------------

extern "C" void kernel_launch(void* const* d_in, const int* in_sizes, int n_in,
                              void* d_out, int out_size)
{
    const float* query = (const float*)d_in[0];
    const float* key_  = (const float*)d_in[1];
    const float* value = (const float*)d_in[2];
    const float* abias = (const float*)d_in[3];
    const float* Wq = (const float*)d_in[4];
    const float* bq = (const float*)d_in[5];
    const float* Wk = (const float*)d_in[6];
    const float* bk = (const float*)d_in[7];
    const float* Wv = (const float*)d_in[8];
    const float* bv = (const float*)d_in[9];
    const float* Wo = (const float*)d_in[10];
    const float* bo = (const float*)d_in[11];
    float* out = (float*)d_out;

    float* vp;
    __nv_bfloat16 *qh, *ql, *kh, *kl, *vth, *vtl, *ah, *al, *wth, *wtl;
    cudaGetSymbolAddress((void**)&vp, g_v);
    cudaGetSymbolAddress((void**)&qh, g_qh);
    cudaGetSymbolAddress((void**)&ql, g_ql);
    cudaGetSymbolAddress((void**)&kh, g_kh);
    cudaGetSymbolAddress((void**)&kl, g_kl);
    cudaGetSymbolAddress((void**)&vth, g_vth);
    cudaGetSymbolAddress((void**)&vtl, g_vtl);
    cudaGetSymbolAddress((void**)&ah, g_ah);
    cudaGetSymbolAddress((void**)&al, g_al);
    cudaGetSymbolAddress((void**)&wth, g_wth);
    cudaGetSymbolAddress((void**)&wtl, g_wtl);

    cudaFuncSetAttribute(gemm_mma_kernel,
                         cudaFuncAttributeMaxDynamicSharedMemorySize,
                         GEMM_SMEM_BYTES);
    cudaFuncSetAttribute(attn_mma_kernel,
                         cudaFuncAttributeMaxDynamicSharedMemorySize,
                         AT_SMEM_BYTES);

    const int nsplit = NB * NS * NE / 4 / 256;
    dim3 gw(16, 1, 16);     // per-head weight transpose: R=1024, C=64, z=16
    dim3 ggemm(64, 4);

    // Q projection -> bf16 hi/lo per-head
    transpose_split_kernel<<<gw, 256>>>(Wq, wth, wtl, ND, NE);
    split_kernel<<<nsplit, 256>>>(query, ah, al);
    gemm_mma_kernel<<<ggemm, 256, GEMM_SMEM_BYTES>>>(ah, al, wth, wtl, bq,
                                                     nullptr, qh, ql, 0);
    // K projection
    transpose_split_kernel<<<gw, 256>>>(Wk, wth, wtl, ND, NE);
    split_kernel<<<nsplit, 256>>>(key_, ah, al);
    gemm_mma_kernel<<<ggemm, 256, GEMM_SMEM_BYTES>>>(ah, al, wth, wtl, bk,
                                                     nullptr, kh, kl, 0);
    // V projection -> fp32 per-head, then transpose+split to [bh][d][s]
    transpose_split_kernel<<<gw, 256>>>(Wv, wth, wtl, ND, NE);
    split_kernel<<<nsplit, 256>>>(value, ah, al);
    gemm_mma_kernel<<<ggemm, 256, GEMM_SMEM_BYTES>>>(ah, al, wth, wtl, bv,
                                                     vp, nullptr, nullptr, 2);
    transpose_split_kernel<<<dim3(32, 1, 64), 256>>>(vp, vth, vtl, ND, NS);

    // attention -> ctx bf16 hi/lo into ah/al
    attn_mma_kernel<<<dim3(16, 64), 128, AT_SMEM_BYTES>>>(
        qh, ql, kh, kl, vth, vtl, abias, ah, al);

    // output projection -> fp32 flat
    transpose_split_kernel<<<dim3(16, 16, 1), 256>>>(Wo, wth, wtl, NE, NE);
    gemm_mma_kernel<<<ggemm, 256, GEMM_SMEM_BYTES>>>(ah, al, wth, wtl, bo,
                                                     out, nullptr, nullptr, 1);
}

// round 7
// speedup vs baseline: 3.2578x; 1.1961x over previous
#include <cuda_runtime.h>
#include <cuda_bf16.h>
#include <cstdint>

#define NB 4
#define NS 2048
#define NE 1024
#define NH 16
#define ND 64

#if defined(__CUDA_ARCH__) && (defined(__CUDA_ARCH_FEAT_SM103_ALL) || \
    defined(__CUDA_ARCH_SPECIFIC__))
#define HAS_TCGEN05 1
#else
#define HAS_TCGEN05 0
#endif

// ---------------------------------------------------------------------------
// Device globals (scratch)
// ---------------------------------------------------------------------------
__device__ __align__(256) float g_v[NB * NH * NS * ND];
__device__ __align__(256) __nv_bfloat16 g_qh[NB * NH * NS * ND];
__device__ __align__(256) __nv_bfloat16 g_ql[NB * NH * NS * ND];
__device__ __align__(256) __nv_bfloat16 g_kh[NB * NH * NS * ND];
__device__ __align__(256) __nv_bfloat16 g_kl[NB * NH * NS * ND];
__device__ __align__(256) __nv_bfloat16 g_vth[NB * NH * ND * NS];
__device__ __align__(256) __nv_bfloat16 g_vtl[NB * NH * ND * NS];
__device__ __align__(256) __nv_bfloat16 g_ah[NB * NS * NE];       // ctx hi/lo
__device__ __align__(256) __nv_bfloat16 g_al[NB * NS * NE];
__device__ __align__(256) __nv_bfloat16 g_wth[3][NE * NE];        // transposed W hi
__device__ __align__(256) __nv_bfloat16 g_wtl[3][NE * NE];        // transposed W lo

// ---------------------------------------------------------------------------
// PTX helpers
// ---------------------------------------------------------------------------
__device__ __forceinline__ uint32_t smem_u32(const void* p) {
    uint32_t a;
    asm("{ .reg .u64 t; cvta.to.shared.u64 t, %1; cvt.u32.u64 %0, t; }"
        : "=r"(a) : "l"(p));
    return a;
}
__device__ __forceinline__ uint32_t elect_one() {
    uint32_t pred;
    asm volatile("{ .reg .pred p; elect.sync _|p, 0xFFFFFFFF; selp.b32 %0,1,0,p; }"
                 : "=r"(pred));
    return pred;
}
#define MBARRIER_INIT(addr, cnt) \
    asm volatile("mbarrier.init.shared.b64 [%0], %1;" :: "r"(addr), "r"(cnt) : "memory")
#define MBARRIER_WAIT_PARITY(addr, par) do {                                   \
    uint32_t _m = (addr), _p = (par), _d;                                      \
    asm volatile("{ .reg .pred p; mbarrier.try_wait.parity.acquire.cta.shared::cta.b64 p, [%1], %2; selp.b32 %0,1,0,p; }" \
        : "=r"(_d) : "r"(_m), "r"(_p) : "memory");                             \
    if (!_d) {                                                                 \
        asm volatile("{ .reg .pred P1; WL_%=: mbarrier.try_wait.parity.acquire.cta.shared::cta.b64 P1, [%0], %1, 0x989680; @P1 bra.uni WD_%=; bra.uni WL_%=; WD_%=: }" \
            :: "r"(_m), "r"(_p) : "memory");                                   \
    } } while (0)
#define TCGEN05_ALLOC(saddr, ncols) \
    asm volatile("tcgen05.alloc.cta_group::1.sync.aligned.shared::cta.b32 [%0], %1;" \
        :: "r"((uint32_t)(saddr)), "r"((uint32_t)(ncols)) : "memory")
#define TCGEN05_DEALLOC(tmem, ncols) \
    asm volatile("tcgen05.dealloc.cta_group::1.sync.aligned.b32 %0, %1;" \
        :: "r"(tmem), "r"((uint32_t)(ncols)))
#define TCGEN05_COMMIT(mbar) \
    asm volatile("tcgen05.commit.cta_group::1.mbarrier::arrive::one.shared::cluster.b64 [%0];" \
        :: "r"((uint32_t)(mbar)) : "memory")
#define TCGEN05_WAIT_LD() asm volatile("tcgen05.wait::ld.sync.aligned;" ::: "memory")
#define TCGEN05_FENCE_AFTER() asm volatile("tcgen05.fence::after_thread_sync;" ::: "memory")
#define TCGEN05_FENCE_BEFORE() asm volatile("tcgen05.fence::before_thread_sync;" ::: "memory")
#define FENCE_ASYNC() asm volatile("fence.proxy.async.shared::cta;" ::: "memory")

#define TCGEN05_LD_X32(r, ta)                                                  \
    asm volatile("tcgen05.ld.sync.aligned.32x32b.x32.b32 "                     \
        "{%0,%1,%2,%3,%4,%5,%6,%7,%8,%9,%10,%11,%12,%13,%14,%15,"             \
        "%16,%17,%18,%19,%20,%21,%22,%23,%24,%25,%26,%27,%28,%29,%30,%31}, [%32];" \
        : "=r"((r)[0]),"=r"((r)[1]),"=r"((r)[2]),"=r"((r)[3]),                 \
          "=r"((r)[4]),"=r"((r)[5]),"=r"((r)[6]),"=r"((r)[7]),                 \
          "=r"((r)[8]),"=r"((r)[9]),"=r"((r)[10]),"=r"((r)[11]),               \
          "=r"((r)[12]),"=r"((r)[13]),"=r"((r)[14]),"=r"((r)[15]),             \
          "=r"((r)[16]),"=r"((r)[17]),"=r"((r)[18]),"=r"((r)[19]),             \
          "=r"((r)[20]),"=r"((r)[21]),"=r"((r)[22]),"=r"((r)[23]),             \
          "=r"((r)[24]),"=r"((r)[25]),"=r"((r)[26]),"=r"((r)[27]),             \
          "=r"((r)[28]),"=r"((r)[29]),"=r"((r)[30]),"=r"((r)[31])              \
        : "r"(ta))

#if HAS_TCGEN05
__device__ __forceinline__ uint64_t make_desc(uint32_t addr) {
    const uint64_t base = (uint64_t(2) << 61) | (uint64_t(1) << 46) |
                          (uint64_t(64) << 32) | (uint64_t(1) << 16);
    return base | ((uint64_t)(addr >> 4) & 0x3FFF);
}
__device__ __forceinline__ void mma_f16_ss(uint32_t d, uint64_t a, uint64_t b,
                                           uint32_t idesc, uint32_t en) {
    asm volatile(
        "{ .reg .pred p; setp.ne.u32 p, %4, 0;\n\t"
        "tcgen05.mma.cta_group::1.kind::f16 [%0], %1, %2, %3, {%5,%5,%5,%5}, p; }"
        :: "r"(d), "l"(a), "l"(b), "r"(idesc), "r"(en), "r"(0u) : "memory");
}
#endif

__device__ __forceinline__ uint32_t pack_bf2(float a, float b) {
    __nv_bfloat162 t = __floats2bfloat162_rn(a, b);
    return *(uint32_t*)&t;
}

// ---------------------------------------------------------------------------
// GEMM common config
// ---------------------------------------------------------------------------
#define GEMM_MT 128
#define GEMM_NT 256
#define GEMM_IDESC ((1u<<4)|(1u<<7)|(1u<<10)|((GEMM_NT/8)<<17)|((GEMM_MT/16)<<24))
#define GEMM_BUF_BYTES 98304
#define GEMM_SMEM_BYTES (1024 + 2 * GEMM_BUF_BYTES)

struct QKVParams {
    const float* A[3];
    const __nv_bfloat16* Wh[3];
    const __nv_bfloat16* Wl[3];
    const float* bias[3];
    float* outV;                 // z==2
    __nv_bfloat16* outH[2];      // z==0,1
    __nv_bfloat16* outL[2];
};

#if HAS_TCGEN05
// B tile loads (pre-split bf16 weights)
template <int NIT>
__device__ __forceinline__ void ld_regs_b(const __nv_bfloat16* __restrict__ g,
                                          int row0, int k0, uint4* r, int tid) {
#pragma unroll
    for (int it = 0; it < NIT; it++) {
        int idx = tid + it * 256;
        int row = idx >> 3, q = idx & 7;
        r[it] = *((const uint4*)(g + (size_t)(row0 + row) * NE + k0) + q);
    }
}
template <int NIT>
__device__ __forceinline__ void st_regs_b(char* s, const uint4* r, int tid) {
#pragma unroll
    for (int it = 0; it < NIT; it++) {
        int idx = tid + it * 256;
        int row = idx >> 3, q = idx & 7;
        uint32_t off = (uint32_t)(row * 128 + q * 16);
        off ^= (off >> 3) & 0x70;
        *(uint4*)(s + off) = r[it];
    }
}
// fp32 A: load 8 floats/thread/group (4 groups), convert hi/lo at store
__device__ __forceinline__ void ld_regs_a32(const float* __restrict__ A,
                                            int m0, int k0, float4 (*r)[2],
                                            int tid) {
#pragma unroll
    for (int g = 0; g < 4; g++) {
        int idx = tid + g * 256;
        int row = idx >> 3, seg = idx & 7;
        const float4* p =
            (const float4*)(A + (size_t)(m0 + row) * NE + k0 + seg * 8);
        r[g][0] = p[0];
        r[g][1] = p[1];
    }
}
__device__ __forceinline__ void st_regs_a32(char* sh, char* sl,
                                            float4 (*r)[2], int tid) {
#pragma unroll
    for (int g = 0; g < 4; g++) {
        int idx = tid + g * 256;
        int row = idx >> 3, seg = idx & 7;
        uint32_t off = (uint32_t)(row * 128 + seg * 16);
        off ^= (off >> 3) & 0x70;
        float f[8] = {r[g][0].x, r[g][0].y, r[g][0].z, r[g][0].w,
                      r[g][1].x, r[g][1].y, r[g][1].z, r[g][1].w};
        float rr[8];
        uint4 h, l;
        uint32_t* hp = &h.x;
        uint32_t* lp = &l.x;
#pragma unroll
        for (int e = 0; e < 8; e++) {
            __nv_bfloat16 hb = __float2bfloat16(f[e]);
            rr[e] = f[e] - __bfloat162float(hb);
        }
#pragma unroll
        for (int p2 = 0; p2 < 4; p2++) {
            hp[p2] = pack_bf2(f[p2 * 2], f[p2 * 2 + 1]);
            lp[p2] = pack_bf2(rr[p2 * 2], rr[p2 * 2 + 1]);
        }
        *(uint4*)(sh + off) = h;
        *(uint4*)(sl + off) = l;
    }
}
// Shared MMA issue for one chunk
__device__ __forceinline__ void gemm_issue(uint32_t tmem, uint32_t ba,
                                           int first, uint32_t mbar) {
    FENCE_ASYNC();
    uint64_t dah = make_desc(ba);
    uint64_t dal = make_desc(ba + 16384);
    uint64_t dbh = make_desc(ba + 32768);
    uint64_t dbl = make_desc(ba + 65536);
#pragma unroll
    for (int s = 0; s < 4; s++) {
        uint64_t o2 = 2u * s;
        mma_f16_ss(tmem, dah + o2, dbh + o2, GEMM_IDESC,
                   (!first || s > 0) ? 1u : 0u);
        mma_f16_ss(tmem, dal + o2, dbh + o2, GEMM_IDESC, 1u);
        mma_f16_ss(tmem, dah + o2, dbl + o2, GEMM_IDESC, 1u);
    }
    TCGEN05_COMMIT(mbar);
}
#endif

// ---------------------------------------------------------------------------
// Fused QKV projection GEMM: z in {0:q, 1:k, 2:v}. fp32 A converted in-kernel.
// grid (64, 4, 3), 256 threads.
// ---------------------------------------------------------------------------
__global__ __launch_bounds__(256) void gemm_qkv_kernel(QKVParams P)
{
#if HAS_TCGEN05
    extern __shared__ __align__(1024) char smem[];
    const uint32_t sb = smem_u32(smem);
    const int tid = threadIdx.x;
    const int wid = tid >> 5, lid = tid & 31;
    const int m0 = blockIdx.x * GEMM_MT;
    const int n0 = blockIdx.y * GEMM_NT;
    const int z = blockIdx.z;
    const float* A = P.A[z];
    const __nv_bfloat16* Bh = P.Wh[z];
    const __nv_bfloat16* Bl = P.Wl[z];
    const float* bias = P.bias[z];

    if (wid == 0) TCGEN05_ALLOC(sb, 512);
    if (tid == 0) { MBARRIER_INIT(sb + 16, 1); MBARRIER_INIT(sb + 24, 1); }
    __syncthreads();
    uint32_t tmem;
    asm volatile("ld.shared.b32 %0, [%1];" : "=r"(tmem) : "r"(sb));

    float4 rA[4][2];
    uint4 rBh[8], rBl[8];
    ld_regs_a32(A, m0, 0, rA, tid);
    ld_regs_b<8>(Bh, n0, 0, rBh, tid);
    ld_regs_b<8>(Bl, n0, 0, rBl, tid);

    int ph0 = 0, ph1 = 0;
    for (int c = 0; c < 16; c++) {
        const int buf = c & 1;
        char* bs = smem + 1024 + buf * GEMM_BUF_BYTES;
        if (c >= 2) {
            if (buf == 0) { MBARRIER_WAIT_PARITY(sb + 16, ph0); ph0 ^= 1; }
            else          { MBARRIER_WAIT_PARITY(sb + 24, ph1); ph1 ^= 1; }
        }
        st_regs_a32(bs, bs + 16384, rA, tid);
        st_regs_b<8>(bs + 32768, rBh, tid);
        st_regs_b<8>(bs + 65536, rBl, tid);
        if (c < 15) {
            const int k1 = (c + 1) * 64;
            ld_regs_a32(A, m0, k1, rA, tid);
            ld_regs_b<8>(Bh, n0, k1, rBh, tid);
            ld_regs_b<8>(Bl, n0, k1, rBl, tid);
        }
        __syncthreads();
        if (wid == 0 && elect_one())
            gemm_issue(tmem, sb + 1024 + buf * GEMM_BUF_BYTES, c == 0,
                       sb + 16 + buf * 8);
    }
    MBARRIER_WAIT_PARITY(sb + 16, ph0);
    MBARRIER_WAIT_PARITY(sb + 24, ph1);
    TCGEN05_FENCE_AFTER();

    const int m = m0 + 32 * (wid & 3) + lid;
    const int b = m >> 11, s_ = m & (NS - 1);
    const int chalf = (wid >> 2) * 128;
#pragma unroll
    for (int i = 0; i < 4; i++) {
        uint32_t r[32];
        TCGEN05_LD_X32(r, tmem + chalf + i * 32);
        TCGEN05_WAIT_LD();
        const int nbase = n0 + chalf + i * 32;
        float vals[32];
        const float4* bp = (const float4*)(bias + nbase);
#pragma unroll
        for (int j4 = 0; j4 < 8; j4++) {
            float4 bb = bp[j4];
            vals[j4 * 4 + 0] = __uint_as_float(r[j4 * 4 + 0]) + bb.x;
            vals[j4 * 4 + 1] = __uint_as_float(r[j4 * 4 + 1]) + bb.y;
            vals[j4 * 4 + 2] = __uint_as_float(r[j4 * 4 + 2]) + bb.z;
            vals[j4 * 4 + 3] = __uint_as_float(r[j4 * 4 + 3]) + bb.w;
        }
        const int h = nbase >> 6, d0 = nbase & 63;
        const size_t base = ((size_t)(b * NH + h) * NS + s_) * ND + d0;
        if (z == 2) {
            float* dst = P.outV + base;
#pragma unroll
            for (int j = 0; j < 32; j += 4)
                *(float4*)(dst + j) =
                    make_float4(vals[j], vals[j+1], vals[j+2], vals[j+3]);
        } else {
#pragma unroll
            for (int c8 = 0; c8 < 4; c8++) {
                uint4 wh, wl;
                uint32_t* ph_ = &wh.x;
                uint32_t* pl_ = &wl.x;
#pragma unroll
                for (int p2 = 0; p2 < 4; p2++) {
                    float a = vals[c8 * 8 + p2 * 2];
                    float bv = vals[c8 * 8 + p2 * 2 + 1];
                    __nv_bfloat16 ha = __float2bfloat16(a);
                    __nv_bfloat16 hb = __float2bfloat16(bv);
                    ph_[p2] = pack_bf2(a, bv);
                    pl_[p2] = pack_bf2(a - __bfloat162float(ha),
                                       bv - __bfloat162float(hb));
                }
                *(uint4*)(P.outH[z] + base + c8 * 8) = wh;
                *(uint4*)(P.outL[z] + base + c8 * 8) = wl;
            }
        }
    }
    __syncthreads();
    if (wid == 0) TCGEN05_DEALLOC(tmem, 512);
#else
    (void)P;
#endif
}

// ---------------------------------------------------------------------------
// Output projection GEMM: A = ctx (bf16 hi/lo), out fp32 flat. grid (64,4).
// ---------------------------------------------------------------------------
__global__ __launch_bounds__(256) void gemm_ctx_kernel(
    const __nv_bfloat16* __restrict__ Ah, const __nv_bfloat16* __restrict__ Al,
    const __nv_bfloat16* __restrict__ Bh, const __nv_bfloat16* __restrict__ Bl,
    const float* __restrict__ bias, float* __restrict__ out)
{
#if HAS_TCGEN05
    extern __shared__ __align__(1024) char smem[];
    const uint32_t sb = smem_u32(smem);
    const int tid = threadIdx.x;
    const int wid = tid >> 5, lid = tid & 31;
    const int m0 = blockIdx.x * GEMM_MT;
    const int n0 = blockIdx.y * GEMM_NT;

    if (wid == 0) TCGEN05_ALLOC(sb, 512);
    if (tid == 0) { MBARRIER_INIT(sb + 16, 1); MBARRIER_INIT(sb + 24, 1); }
    __syncthreads();
    uint32_t tmem;
    asm volatile("ld.shared.b32 %0, [%1];" : "=r"(tmem) : "r"(sb));

    uint4 rAh[4], rAl[4], rBh[8], rBl[8];
    auto ldA = [&](int k0) {
#pragma unroll
        for (int it = 0; it < 4; it++) {
            int idx = tid + it * 256;
            int row = idx >> 3, q = idx & 7;
            rAh[it] = *((const uint4*)(Ah + (size_t)(m0 + row) * NE + k0) + q);
            rAl[it] = *((const uint4*)(Al + (size_t)(m0 + row) * NE + k0) + q);
        }
    };
    auto stA = [&](char* sh, char* sl) {
#pragma unroll
        for (int it = 0; it < 4; it++) {
            int idx = tid + it * 256;
            int row = idx >> 3, q = idx & 7;
            uint32_t off = (uint32_t)(row * 128 + q * 16);
            off ^= (off >> 3) & 0x70;
            *(uint4*)(sh + off) = rAh[it];
            *(uint4*)(sl + off) = rAl[it];
        }
    };
    ldA(0);
    ld_regs_b<8>(Bh, n0, 0, rBh, tid);
    ld_regs_b<8>(Bl, n0, 0, rBl, tid);

    int ph0 = 0, ph1 = 0;
    for (int c = 0; c < 16; c++) {
        const int buf = c & 1;
        char* bs = smem + 1024 + buf * GEMM_BUF_BYTES;
        if (c >= 2) {
            if (buf == 0) { MBARRIER_WAIT_PARITY(sb + 16, ph0); ph0 ^= 1; }
            else          { MBARRIER_WAIT_PARITY(sb + 24, ph1); ph1 ^= 1; }
        }
        stA(bs, bs + 16384);
        st_regs_b<8>(bs + 32768, rBh, tid);
        st_regs_b<8>(bs + 65536, rBl, tid);
        if (c < 15) {
            const int k1 = (c + 1) * 64;
            ldA(k1);
            ld_regs_b<8>(Bh, n0, k1, rBh, tid);
            ld_regs_b<8>(Bl, n0, k1, rBl, tid);
        }
        __syncthreads();
        if (wid == 0 && elect_one())
            gemm_issue(tmem, sb + 1024 + buf * GEMM_BUF_BYTES, c == 0,
                       sb + 16 + buf * 8);
    }
    MBARRIER_WAIT_PARITY(sb + 16, ph0);
    MBARRIER_WAIT_PARITY(sb + 24, ph1);
    TCGEN05_FENCE_AFTER();

    const int m = m0 + 32 * (wid & 3) + lid;
    const int chalf = (wid >> 2) * 128;
#pragma unroll
    for (int i = 0; i < 4; i++) {
        uint32_t r[32];
        TCGEN05_LD_X32(r, tmem + chalf + i * 32);
        TCGEN05_WAIT_LD();
        const int nbase = n0 + chalf + i * 32;
        const float4* bp = (const float4*)(bias + nbase);
        float* dst = out + ((size_t)m * NE + nbase);
#pragma unroll
        for (int j4 = 0; j4 < 8; j4++) {
            float4 bb = bp[j4];
            float4 w;
            w.x = __uint_as_float(r[j4 * 4 + 0]) + bb.x;
            w.y = __uint_as_float(r[j4 * 4 + 1]) + bb.y;
            w.z = __uint_as_float(r[j4 * 4 + 2]) + bb.z;
            w.w = __uint_as_float(r[j4 * 4 + 3]) + bb.w;
            *(float4*)(dst + j4 * 4) = w;
        }
    }
    __syncthreads();
    if (wid == 0) TCGEN05_DEALLOC(tmem, 512);
#else
    (void)Ah;(void)Al;(void)Bh;(void)Bl;(void)bias;(void)out;
#endif
}

// ---------------------------------------------------------------------------
// tcgen05 flash attention, max-free softmax, decoupled S/O pipelines.
// 128 q-rows per CTA, 32 kv tiles of 64, triple-buffered KV, 128 threads.
// ---------------------------------------------------------------------------
#define AT_Q   1024
#define AT_QL  (AT_Q + 16384)
#define AT_STG (AT_QL + 16384)          // 3 stages x 32KB: Kh,Kl,Vh,Vl (8KB each)
#define AT_PH  (AT_STG + 3 * 32768)
#define AT_PL  (AT_PH + 16384)
#define AT_SMEM_BYTES (AT_PL + 16384)   // ~161KB
#define AT_IDESC ((1u<<4)|(1u<<7)|(1u<<10)|((64/8)<<17)|((128/16)<<24))

__global__ __launch_bounds__(128) void attn_mma_kernel(
    const __nv_bfloat16* __restrict__ qh, const __nv_bfloat16* __restrict__ ql,
    const __nv_bfloat16* __restrict__ kh, const __nv_bfloat16* __restrict__ kl,
    const __nv_bfloat16* __restrict__ vth, const __nv_bfloat16* __restrict__ vtl,
    const float* __restrict__ bias,
    __nv_bfloat16* __restrict__ ctx_h, __nv_bfloat16* __restrict__ ctx_l)
{
#if HAS_TCGEN05
    extern __shared__ __align__(1024) char smem[];
    const uint32_t sb = smem_u32(smem);
    const int tid = threadIdx.x;
    const int wid = tid >> 5, lid = tid & 31;
    const int s0 = blockIdx.x * 128;
    const int bh = blockIdx.y;

    const __nv_bfloat16* qhp = qh + ((size_t)bh * NS + s0) * ND;
    const __nv_bfloat16* qlp = ql + ((size_t)bh * NS + s0) * ND;
    const __nv_bfloat16* khp = kh + (size_t)bh * NS * ND;
    const __nv_bfloat16* klp = kl + (size_t)bh * NS * ND;
    const __nv_bfloat16* vhp = vth + (size_t)bh * ND * NS;
    const __nv_bfloat16* vlp = vtl + (size_t)bh * ND * NS;

    if (wid == 0) TCGEN05_ALLOC(sb, 128);
    if (tid == 0) { MBARRIER_INIT(sb + 16, 1); MBARRIER_INIT(sb + 24, 1); }
    __syncthreads();
    uint32_t tmem;
    asm volatile("ld.shared.b32 %0, [%1];" : "=r"(tmem) : "r"(sb));

#pragma unroll
    for (int it = 0; it < 8; it++) {
        int idx = tid + it * 128;
        int row = idx >> 3, q = idx & 7;
        uint32_t off = (uint32_t)(row * 128 + q * 16);
        off ^= (off >> 3) & 0x70;
        *(uint4*)(smem + AT_Q + off)  = *((const uint4*)(qhp + (size_t)row * ND) + q);
        *(uint4*)(smem + AT_QL + off) = *((const uint4*)(qlp + (size_t)row * ND) + q);
    }

    auto ld_kv = [&](int t, int stg) {
        char* ks = smem + AT_STG + stg * 32768;
        const __nv_bfloat16* kh_t = khp + (size_t)t * 64 * ND;
        const __nv_bfloat16* kl_t = klp + (size_t)t * 64 * ND;
        const __nv_bfloat16* vh_t = vhp + (size_t)t * 64;
        const __nv_bfloat16* vl_t = vlp + (size_t)t * 64;
#pragma unroll
        for (int it = 0; it < 4; it++) {
            int idx = tid + it * 128;
            int row = idx >> 3, q = idx & 7;
            uint32_t off = (uint32_t)(row * 128 + q * 16);
            off ^= (off >> 3) & 0x70;
            *(uint4*)(ks + off)         = *((const uint4*)(kh_t + (size_t)row * ND) + q);
            *(uint4*)(ks + 8192 + off)  = *((const uint4*)(kl_t + (size_t)row * ND) + q);
            *(uint4*)(ks + 16384 + off) = *((const uint4*)(vh_t + (size_t)row * NS) + q);
            *(uint4*)(ks + 24576 + off) = *((const uint4*)(vl_t + (size_t)row * NS) + q);
        }
    };

    const uint64_t dq_h = make_desc(sb + AT_Q);
    const uint64_t dq_l = make_desc(sb + AT_QL);
    const uint64_t dp_h = make_desc(sb + AT_PH);
    const uint64_t dp_l = make_desc(sb + AT_PL);

    // S(t) overwrites its accumulator each tile: enable = (s4 > 0) ONLY.
    auto issue_S = [&](int t) {
        const uint32_t ks = sb + AT_STG + (t % 3) * 32768;
        uint64_t dk_h = make_desc(ks), dk_l = make_desc(ks + 8192);
#pragma unroll
        for (int s4 = 0; s4 < 4; s4++) {
            uint64_t o2 = 2u * s4;
            mma_f16_ss(tmem, dq_h + o2, dk_h + o2, AT_IDESC, s4 > 0 ? 1u : 0u);
            mma_f16_ss(tmem, dq_l + o2, dk_h + o2, AT_IDESC, 1u);
            mma_f16_ss(tmem, dq_h + o2, dk_l + o2, AT_IDESC, 1u);
        }
    };
    auto issue_O = [&](int t) {
        const uint32_t ks = sb + AT_STG + (t % 3) * 32768;
        uint64_t dv_h = make_desc(ks + 16384), dv_l = make_desc(ks + 24576);
#pragma unroll
        for (int s4 = 0; s4 < 4; s4++) {
            uint64_t o2 = 2u * s4;
            mma_f16_ss(tmem + 64, dp_h + o2, dv_h + o2, AT_IDESC,
                       (t > 0 || s4 > 0) ? 1u : 0u);
            mma_f16_ss(tmem + 64, dp_l + o2, dv_h + o2, AT_IDESC, 1u);
            mma_f16_ss(tmem + 64, dp_h + o2, dv_l + o2, AT_IDESC, 1u);
        }
    };

    ld_kv(0, 0);
    __syncthreads();
    if (wid == 0 && elect_one()) {
        FENCE_ASYNC();
        issue_S(0);
        TCGEN05_COMMIT(sb + 16);
    }

    const int row = 32 * wid + lid;
    const float* brow = bias + (size_t)(s0 + row) * NS;
    float lsum = 0.f;
    int ph_s = 0, ph_o = 0;

    for (int t = 0; t < 32; t++) {
        if (t + 1 < 32) ld_kv(t + 1, (t + 1) % 3);

        float4 bb[16];
        const float4* bp = (const float4*)(brow + t * 64);
#pragma unroll
        for (int i = 0; i < 16; i++) bb[i] = bp[i];

        MBARRIER_WAIT_PARITY(sb + 16, ph_s);   // S(t) done
        ph_s ^= 1;
        TCGEN05_FENCE_AFTER();

        float p[64];
#pragma unroll
        for (int hf = 0; hf < 2; hf++) {
            uint32_t r[32];
            TCGEN05_LD_X32(r, tmem + hf * 32);
            TCGEN05_WAIT_LD();
#pragma unroll
            for (int j4 = 0; j4 < 8; j4++) {
                float4 b4 = bb[hf * 8 + j4];
                int o = hf * 32 + j4 * 4;
                p[o+0] = __expf(fmaf(__uint_as_float(r[j4*4+0]), 0.125f, b4.x));
                p[o+1] = __expf(fmaf(__uint_as_float(r[j4*4+1]), 0.125f, b4.y));
                p[o+2] = __expf(fmaf(__uint_as_float(r[j4*4+2]), 0.125f, b4.z));
                p[o+3] = __expf(fmaf(__uint_as_float(r[j4*4+3]), 0.125f, b4.w));
                lsum += p[o+0] + p[o+1] + p[o+2] + p[o+3];
            }
        }

        if (t >= 1) {                          // O(t-1) done reading P
            MBARRIER_WAIT_PARITY(sb + 24, ph_o);
            ph_o ^= 1;
        }
#pragma unroll
        for (int c4 = 0; c4 < 8; c4++) {
            uint4 wh, wl;
            uint32_t* phh = &wh.x;
            uint32_t* pll = &wl.x;
#pragma unroll
            for (int p2 = 0; p2 < 4; p2++) {
                float a = p[c4 * 8 + p2 * 2];
                float c = p[c4 * 8 + p2 * 2 + 1];
                __nv_bfloat16 ha = __float2bfloat16(a);
                __nv_bfloat16 hc = __float2bfloat16(c);
                phh[p2] = pack_bf2(a, c);
                pll[p2] = pack_bf2(a - __bfloat162float(ha),
                                   c - __bfloat162float(hc));
            }
            uint32_t off = (uint32_t)(row * 128 + c4 * 16);
            off ^= (off >> 3) & 0x70;
            *(uint4*)(smem + AT_PH + off) = wh;
            *(uint4*)(smem + AT_PL + off) = wl;
        }
        __syncthreads();                        // P + KV(t+1) visible

        if (wid == 0 && elect_one()) {
            FENCE_ASYNC();
            if (t + 1 < 32) {
                issue_S(t + 1);
                TCGEN05_COMMIT(sb + 16);       // bar_s: S(t+1)
            }
            issue_O(t);
            TCGEN05_COMMIT(sb + 24);           // bar_o: O(t)
        }
    }
    MBARRIER_WAIT_PARITY(sb + 24, ph_o);       // O(31)
    TCGEN05_FENCE_AFTER();

    const float inv = 1.f / lsum;
    const int b = bh >> 4, h = bh & 15;
    const size_t obase = ((size_t)b * NS + s0 + row) * NE + h * ND;
#pragma unroll
    for (int hf = 0; hf < 2; hf++) {
        uint32_t r[32];
        TCGEN05_LD_X32(r, tmem + 64 + hf * 32);
        TCGEN05_WAIT_LD();
#pragma unroll
        for (int c8 = 0; c8 < 4; c8++) {
            uint4 wh, wl;
            uint32_t* phh = &wh.x;
            uint32_t* pll = &wl.x;
#pragma unroll
            for (int p2 = 0; p2 < 4; p2++) {
                float a = __uint_as_float(r[c8 * 8 + p2 * 2]) * inv;
                float c = __uint_as_float(r[c8 * 8 + p2 * 2 + 1]) * inv;
                __nv_bfloat16 ha = __float2bfloat16(a);
                __nv_bfloat16 hc = __float2bfloat16(c);
                phh[p2] = pack_bf2(a, c);
                pll[p2] = pack_bf2(a - __bfloat162float(ha),
                                   c - __bfloat162float(hc));
            }
            *(uint4*)(ctx_h + obase + hf * 32 + c8 * 8) = wh;
            *(uint4*)(ctx_l + obase + hf * 32 + c8 * 8) = wl;
        }
    }
    TCGEN05_FENCE_BEFORE();
    __syncthreads();
    if (wid == 0) TCGEN05_DEALLOC(tmem, 128);
#else
    (void)qh;(void)ql;(void)kh;(void)kl;(void)vth;(void)vtl;(void)bias;(void)ctx_h;(void)ctx_l;
#endif
}

// ---------------------------------------------------------------------------
// transpose + split: in[z][R][C] fp32 -> out[(z*C + c)][R] bf16 hi/lo
// ---------------------------------------------------------------------------
__global__ __launch_bounds__(256) void transpose_split_kernel(
    const float* __restrict__ in, __nv_bfloat16* __restrict__ oh,
    __nv_bfloat16* __restrict__ ol, int C, int R)
{
    __shared__ float t[64][65];
    const float* inz = in + (size_t)blockIdx.z * R * C;
    const int r0 = blockIdx.x * 64, c0 = blockIdx.y * 64;
    const int tid = threadIdx.x;
#pragma unroll
    for (int it = 0; it < 16; it++) {
        int idx = tid + it * 256;
        int rr = idx >> 6, cc = idx & 63;
        t[rr][cc] = inz[(size_t)(r0 + rr) * C + c0 + cc];
    }
    __syncthreads();
#pragma unroll
    for (int it = 0; it < 16; it++) {
        int idx = tid + it * 256;
        int cc = idx >> 6, rr = idx & 63;
        float x = t[rr][cc];
        __nv_bfloat16 hi = __float2bfloat16(x);
        size_t o = (size_t)(blockIdx.z * C + c0 + cc) * R + r0 + rr;
        oh[o] = hi;
        ol[o] = __float2bfloat16(x - __bfloat162float(hi));
    }
}

// ---------------------------------------------------------------------------

extern "C" void kernel_launch(void* const* d_in, const int* in_sizes, int n_in,
                              void* d_out, int out_size)
{
    const float* query = (const float*)d_in[0];
    const float* key_  = (const float*)d_in[1];
    const float* value = (const float*)d_in[2];
    const float* abias = (const float*)d_in[3];
    const float* Wq = (const float*)d_in[4];
    const float* bq = (const float*)d_in[5];
    const float* Wk = (const float*)d_in[6];
    const float* bk = (const float*)d_in[7];
    const float* Wv = (const float*)d_in[8];
    const float* bv = (const float*)d_in[9];
    const float* Wo = (const float*)d_in[10];
    const float* bo = (const float*)d_in[11];
    float* out = (float*)d_out;

    float* vp;
    __nv_bfloat16 *qh, *ql, *kh, *kl, *vth, *vtl, *ah, *al, *wth, *wtl;
    cudaGetSymbolAddress((void**)&vp, g_v);
    cudaGetSymbolAddress((void**)&qh, g_qh);
    cudaGetSymbolAddress((void**)&ql, g_ql);
    cudaGetSymbolAddress((void**)&kh, g_kh);
    cudaGetSymbolAddress((void**)&kl, g_kl);
    cudaGetSymbolAddress((void**)&vth, g_vth);
    cudaGetSymbolAddress((void**)&vtl, g_vtl);
    cudaGetSymbolAddress((void**)&ah, g_ah);
    cudaGetSymbolAddress((void**)&al, g_al);
    cudaGetSymbolAddress((void**)&wth, g_wth);
    cudaGetSymbolAddress((void**)&wtl, g_wtl);

    cudaFuncSetAttribute(gemm_qkv_kernel,
                         cudaFuncAttributeMaxDynamicSharedMemorySize,
                         GEMM_SMEM_BYTES);
    cudaFuncSetAttribute(gemm_ctx_kernel,
                         cudaFuncAttributeMaxDynamicSharedMemorySize,
                         GEMM_SMEM_BYTES);
    cudaFuncSetAttribute(attn_mma_kernel,
                         cudaFuncAttributeMaxDynamicSharedMemorySize,
                         AT_SMEM_BYTES);

    // weight transposes (hi/lo) into 3 persistent buffers
    dim3 gw(16, 1, 16);
    transpose_split_kernel<<<gw, 256>>>(Wq, wth + 0 * NE * NE, wtl + 0 * NE * NE, ND, NE);
    transpose_split_kernel<<<gw, 256>>>(Wk, wth + 1 * NE * NE, wtl + 1 * NE * NE, ND, NE);
    transpose_split_kernel<<<gw, 256>>>(Wv, wth + 2 * NE * NE, wtl + 2 * NE * NE, ND, NE);

    // fused QKV projections (fp32 A converted in-kernel)
    QKVParams P;
    P.A[0] = query; P.A[1] = key_; P.A[2] = value;
    P.Wh[0] = wth; P.Wh[1] = wth + NE * NE; P.Wh[2] = wth + 2 * NE * NE;
    P.Wl[0] = wtl; P.Wl[1] = wtl + NE * NE; P.Wl[2] = wtl + 2 * NE * NE;
    P.bias[0] = bq; P.bias[1] = bk; P.bias[2] = bv;
    P.outV = vp;
    P.outH[0] = qh; P.outH[1] = kh;
    P.outL[0] = ql; P.outL[1] = kl;
    gemm_qkv_kernel<<<dim3(64, 4, 3), 256, GEMM_SMEM_BYTES>>>(P);

    // V^T split for PV MMA
    transpose_split_kernel<<<dim3(32, 1, 64), 256>>>(vp, vth, vtl, ND, NS);

    // attention -> ctx bf16 hi/lo
    attn_mma_kernel<<<dim3(16, 64), 128, AT_SMEM_BYTES>>>(
        qh, ql, kh, kl, vth, vtl, abias, ah, al);

    // output projection
    transpose_split_kernel<<<dim3(16, 16, 1), 256>>>(Wo, wth, wtl, NE, NE);
    gemm_ctx_kernel<<<dim3(64, 4), 256, GEMM_SMEM_BYTES>>>(ah, al, wth, wtl, bo, out);
}

// round 9
// speedup vs baseline: 3.5297x; 1.0835x over previous
#include <cuda_runtime.h>
#include <cuda_bf16.h>
#include <cstdint>

#define NB 4
#define NS 2048
#define NE 1024
#define NH 16
#define ND 64

#if defined(__CUDA_ARCH__) && (defined(__CUDA_ARCH_FEAT_SM103_ALL) || \
    defined(__CUDA_ARCH_SPECIFIC__))
#define HAS_TCGEN05 1
#else
#define HAS_TCGEN05 0
#endif

// ---------------------------------------------------------------------------
// Device globals (scratch)
// ---------------------------------------------------------------------------
__device__ __align__(256) float g_v[NB * NH * NS * ND];
__device__ __align__(256) __nv_bfloat16 g_qh[NB * NH * NS * ND];
__device__ __align__(256) __nv_bfloat16 g_ql[NB * NH * NS * ND];
__device__ __align__(256) __nv_bfloat16 g_kh[NB * NH * NS * ND];
__device__ __align__(256) __nv_bfloat16 g_kl[NB * NH * NS * ND];
__device__ __align__(256) __nv_bfloat16 g_vth[NB * NH * ND * NS];
__device__ __align__(256) __nv_bfloat16 g_vtl[NB * NH * ND * NS];
__device__ __align__(256) __nv_bfloat16 g_ah[NB * NS * NE];       // ctx hi/lo
__device__ __align__(256) __nv_bfloat16 g_al[NB * NS * NE];
__device__ __align__(256) __nv_bfloat16 g_wth[3][NE * NE];
__device__ __align__(256) __nv_bfloat16 g_wtl[3][NE * NE];

// ---------------------------------------------------------------------------
// PTX helpers
// ---------------------------------------------------------------------------
__device__ __forceinline__ uint32_t smem_u32(const void* p) {
    uint32_t a;
    asm("{ .reg .u64 t; cvta.to.shared.u64 t, %1; cvt.u32.u64 %0, t; }"
        : "=r"(a) : "l"(p));
    return a;
}
__device__ __forceinline__ uint32_t elect_one() {
    uint32_t pred;
    asm volatile("{ .reg .pred p; elect.sync _|p, 0xFFFFFFFF; selp.b32 %0,1,0,p; }"
                 : "=r"(pred));
    return pred;
}
#define MBARRIER_INIT(addr, cnt) \
    asm volatile("mbarrier.init.shared.b64 [%0], %1;" :: "r"(addr), "r"(cnt) : "memory")
#define MBARRIER_WAIT_PARITY(addr, par) do {                                   \
    uint32_t _m = (addr), _p = (par), _d;                                      \
    asm volatile("{ .reg .pred p; mbarrier.try_wait.parity.acquire.cta.shared::cta.b64 p, [%1], %2; selp.b32 %0,1,0,p; }" \
        : "=r"(_d) : "r"(_m), "r"(_p) : "memory");                             \
    if (!_d) {                                                                 \
        asm volatile("{ .reg .pred P1; WL_%=: mbarrier.try_wait.parity.acquire.cta.shared::cta.b64 P1, [%0], %1, 0x989680; @P1 bra.uni WD_%=; bra.uni WL_%=; WD_%=: }" \
            :: "r"(_m), "r"(_p) : "memory");                                   \
    } } while (0)
#define TCGEN05_ALLOC(saddr, ncols) \
    asm volatile("tcgen05.alloc.cta_group::1.sync.aligned.shared::cta.b32 [%0], %1;" \
        :: "r"((uint32_t)(saddr)), "r"((uint32_t)(ncols)) : "memory")
#define TCGEN05_DEALLOC(tmem, ncols) \
    asm volatile("tcgen05.dealloc.cta_group::1.sync.aligned.b32 %0, %1;" \
        :: "r"(tmem), "r"((uint32_t)(ncols)))
#define TCGEN05_COMMIT(mbar) \
    asm volatile("tcgen05.commit.cta_group::1.mbarrier::arrive::one.shared::cluster.b64 [%0];" \
        :: "r"((uint32_t)(mbar)) : "memory")
#define TCGEN05_WAIT_LD() asm volatile("tcgen05.wait::ld.sync.aligned;" ::: "memory")
#define TCGEN05_FENCE_AFTER() asm volatile("tcgen05.fence::after_thread_sync;" ::: "memory")
#define TCGEN05_FENCE_BEFORE() asm volatile("tcgen05.fence::before_thread_sync;" ::: "memory")
#define FENCE_ASYNC() asm volatile("fence.proxy.async.shared::cta;" ::: "memory")

#define TCGEN05_LD_X32(r, ta)                                                  \
    asm volatile("tcgen05.ld.sync.aligned.32x32b.x32.b32 "                     \
        "{%0,%1,%2,%3,%4,%5,%6,%7,%8,%9,%10,%11,%12,%13,%14,%15,"             \
        "%16,%17,%18,%19,%20,%21,%22,%23,%24,%25,%26,%27,%28,%29,%30,%31}, [%32];" \
        : "=r"((r)[0]),"=r"((r)[1]),"=r"((r)[2]),"=r"((r)[3]),                 \
          "=r"((r)[4]),"=r"((r)[5]),"=r"((r)[6]),"=r"((r)[7]),                 \
          "=r"((r)[8]),"=r"((r)[9]),"=r"((r)[10]),"=r"((r)[11]),               \
          "=r"((r)[12]),"=r"((r)[13]),"=r"((r)[14]),"=r"((r)[15]),             \
          "=r"((r)[16]),"=r"((r)[17]),"=r"((r)[18]),"=r"((r)[19]),             \
          "=r"((r)[20]),"=r"((r)[21]),"=r"((r)[22]),"=r"((r)[23]),             \
          "=r"((r)[24]),"=r"((r)[25]),"=r"((r)[26]),"=r"((r)[27]),             \
          "=r"((r)[28]),"=r"((r)[29]),"=r"((r)[30]),"=r"((r)[31])              \
        : "r"(ta))

#if HAS_TCGEN05
__device__ __forceinline__ uint64_t make_desc(uint32_t addr) {
    const uint64_t base = (uint64_t(2) << 61) | (uint64_t(1) << 46) |
                          (uint64_t(64) << 32) | (uint64_t(1) << 16);
    return base | ((uint64_t)(addr >> 4) & 0x3FFF);
}
__device__ __forceinline__ void mma_f16_ss(uint32_t d, uint64_t a, uint64_t b,
                                           uint32_t idesc, uint32_t en) {
    asm volatile(
        "{ .reg .pred p; setp.ne.u32 p, %4, 0;\n\t"
        "tcgen05.mma.cta_group::1.kind::f16 [%0], %1, %2, %3, {%5,%5,%5,%5}, p; }"
        :: "r"(d), "l"(a), "l"(b), "r"(idesc), "r"(en), "r"(0u) : "memory");
}
#endif

__device__ __forceinline__ uint32_t pack_bf2(float a, float b) {
    __nv_bfloat162 t = __floats2bfloat162_rn(a, b);
    return *(uint32_t*)&t;
}

// ---------------------------------------------------------------------------
// GEMM common config (R7-proven SS mode)
// ---------------------------------------------------------------------------
#define GEMM_MT 128
#define GEMM_NT 256
#define GEMM_IDESC ((1u<<4)|(1u<<7)|(1u<<10)|((GEMM_NT/8)<<17)|((GEMM_MT/16)<<24))
#define GEMM_BUF_BYTES 98304
#define GEMM_SMEM_BYTES (1024 + 2 * GEMM_BUF_BYTES)

struct QKVParams {
    const float* A[3];
    const __nv_bfloat16* Wh[3];
    const __nv_bfloat16* Wl[3];
    const float* bias[3];
    float* outV;                 // z==2
    __nv_bfloat16* outH[2];      // z==0,1
    __nv_bfloat16* outL[2];
};

#if HAS_TCGEN05
template <int NIT>
__device__ __forceinline__ void ld_regs_b(const __nv_bfloat16* __restrict__ g,
                                          int row0, int k0, uint4* r, int tid) {
#pragma unroll
    for (int it = 0; it < NIT; it++) {
        int idx = tid + it * 256;
        int row = idx >> 3, q = idx & 7;
        r[it] = *((const uint4*)(g + (size_t)(row0 + row) * NE + k0) + q);
    }
}
template <int NIT>
__device__ __forceinline__ void st_regs_b(char* s, const uint4* r, int tid) {
#pragma unroll
    for (int it = 0; it < NIT; it++) {
        int idx = tid + it * 256;
        int row = idx >> 3, q = idx & 7;
        uint32_t off = (uint32_t)(row * 128 + q * 16);
        off ^= (off >> 3) & 0x70;
        *(uint4*)(s + off) = r[it];
    }
}
__device__ __forceinline__ void ld_regs_a32(const float* __restrict__ A,
                                            int m0, int k0, float4 (*r)[2],
                                            int tid) {
#pragma unroll
    for (int g = 0; g < 4; g++) {
        int idx = tid + g * 256;
        int row = idx >> 3, seg = idx & 7;
        const float4* p =
            (const float4*)(A + (size_t)(m0 + row) * NE + k0 + seg * 8);
        r[g][0] = p[0];
        r[g][1] = p[1];
    }
}
__device__ __forceinline__ void st_regs_a32(char* sh, char* sl,
                                            float4 (*r)[2], int tid) {
#pragma unroll
    for (int g = 0; g < 4; g++) {
        int idx = tid + g * 256;
        int row = idx >> 3, seg = idx & 7;
        uint32_t off = (uint32_t)(row * 128 + seg * 16);
        off ^= (off >> 3) & 0x70;
        float f[8] = {r[g][0].x, r[g][0].y, r[g][0].z, r[g][0].w,
                      r[g][1].x, r[g][1].y, r[g][1].z, r[g][1].w};
        float rr[8];
        uint4 h, l;
        uint32_t* hp = &h.x;
        uint32_t* lp = &l.x;
#pragma unroll
        for (int e = 0; e < 8; e++) {
            __nv_bfloat16 hb = __float2bfloat16(f[e]);
            rr[e] = f[e] - __bfloat162float(hb);
        }
#pragma unroll
        for (int p2 = 0; p2 < 4; p2++) {
            hp[p2] = pack_bf2(f[p2 * 2], f[p2 * 2 + 1]);
            lp[p2] = pack_bf2(rr[p2 * 2], rr[p2 * 2 + 1]);
        }
        *(uint4*)(sh + off) = h;
        *(uint4*)(sl + off) = l;
    }
}
__device__ __forceinline__ void gemm_issue(uint32_t tmem, uint32_t ba,
                                           int first, uint32_t mbar) {
    FENCE_ASYNC();
    uint64_t dah = make_desc(ba);
    uint64_t dal = make_desc(ba + 16384);
    uint64_t dbh = make_desc(ba + 32768);
    uint64_t dbl = make_desc(ba + 65536);
#pragma unroll
    for (int s = 0; s < 4; s++) {
        uint64_t o2 = 2u * s;
        mma_f16_ss(tmem, dah + o2, dbh + o2, GEMM_IDESC,
                   (!first || s > 0) ? 1u : 0u);
        mma_f16_ss(tmem, dal + o2, dbh + o2, GEMM_IDESC, 1u);
        mma_f16_ss(tmem, dah + o2, dbl + o2, GEMM_IDESC, 1u);
    }
    TCGEN05_COMMIT(mbar);
}
#endif

// ---------------------------------------------------------------------------
// Fused QKV projection GEMM (R7, SS): grid (64, 4, 3), 256 threads.
// ---------------------------------------------------------------------------
__global__ __launch_bounds__(256) void gemm_qkv_kernel(QKVParams P)
{
#if HAS_TCGEN05
    extern __shared__ __align__(1024) char smem[];
    const uint32_t sb = smem_u32(smem);
    const int tid = threadIdx.x;
    const int wid = tid >> 5, lid = tid & 31;
    const int m0 = blockIdx.x * GEMM_MT;
    const int n0 = blockIdx.y * GEMM_NT;
    const int z = blockIdx.z;
    const float* A = P.A[z];
    const __nv_bfloat16* Bh = P.Wh[z];
    const __nv_bfloat16* Bl = P.Wl[z];
    const float* bias = P.bias[z];

    if (wid == 0) TCGEN05_ALLOC(sb, 512);
    if (tid == 0) { MBARRIER_INIT(sb + 16, 1); MBARRIER_INIT(sb + 24, 1); }
    __syncthreads();
    uint32_t tmem;
    asm volatile("ld.shared.b32 %0, [%1];" : "=r"(tmem) : "r"(sb));

    float4 rA[4][2];
    uint4 rBh[8], rBl[8];
    ld_regs_a32(A, m0, 0, rA, tid);
    ld_regs_b<8>(Bh, n0, 0, rBh, tid);
    ld_regs_b<8>(Bl, n0, 0, rBl, tid);

    int ph0 = 0, ph1 = 0;
    for (int c = 0; c < 16; c++) {
        const int buf = c & 1;
        char* bs = smem + 1024 + buf * GEMM_BUF_BYTES;
        if (c >= 2) {
            if (buf == 0) { MBARRIER_WAIT_PARITY(sb + 16, ph0); ph0 ^= 1; }
            else          { MBARRIER_WAIT_PARITY(sb + 24, ph1); ph1 ^= 1; }
        }
        st_regs_a32(bs, bs + 16384, rA, tid);
        st_regs_b<8>(bs + 32768, rBh, tid);
        st_regs_b<8>(bs + 65536, rBl, tid);
        if (c < 15) {
            const int k1 = (c + 1) * 64;
            ld_regs_a32(A, m0, k1, rA, tid);
            ld_regs_b<8>(Bh, n0, k1, rBh, tid);
            ld_regs_b<8>(Bl, n0, k1, rBl, tid);
        }
        __syncthreads();
        if (wid == 0 && elect_one())
            gemm_issue(tmem, sb + 1024 + buf * GEMM_BUF_BYTES, c == 0,
                       sb + 16 + buf * 8);
    }
    MBARRIER_WAIT_PARITY(sb + 16, ph0);
    MBARRIER_WAIT_PARITY(sb + 24, ph1);
    TCGEN05_FENCE_AFTER();

    const int m = m0 + 32 * (wid & 3) + lid;
    const int b = m >> 11, s_ = m & (NS - 1);
    const int chalf = (wid >> 2) * 128;
#pragma unroll
    for (int i = 0; i < 4; i++) {
        uint32_t r[32];
        TCGEN05_LD_X32(r, tmem + chalf + i * 32);
        TCGEN05_WAIT_LD();
        const int nbase = n0 + chalf + i * 32;
        float vals[32];
        const float4* bp = (const float4*)(bias + nbase);
#pragma unroll
        for (int j4 = 0; j4 < 8; j4++) {
            float4 bb = bp[j4];
            vals[j4 * 4 + 0] = __uint_as_float(r[j4 * 4 + 0]) + bb.x;
            vals[j4 * 4 + 1] = __uint_as_float(r[j4 * 4 + 1]) + bb.y;
            vals[j4 * 4 + 2] = __uint_as_float(r[j4 * 4 + 2]) + bb.z;
            vals[j4 * 4 + 3] = __uint_as_float(r[j4 * 4 + 3]) + bb.w;
        }
        const int h = nbase >> 6, d0 = nbase & 63;
        const size_t base = ((size_t)(b * NH + h) * NS + s_) * ND + d0;
        if (z == 2) {
            float* dst = P.outV + base;
#pragma unroll
            for (int j = 0; j < 32; j += 4)
                *(float4*)(dst + j) =
                    make_float4(vals[j], vals[j+1], vals[j+2], vals[j+3]);
        } else {
#pragma unroll
            for (int c8 = 0; c8 < 4; c8++) {
                uint4 wh, wl;
                uint32_t* ph_ = &wh.x;
                uint32_t* pl_ = &wl.x;
#pragma unroll
                for (int p2 = 0; p2 < 4; p2++) {
                    float a = vals[c8 * 8 + p2 * 2];
                    float bv = vals[c8 * 8 + p2 * 2 + 1];
                    __nv_bfloat16 ha = __float2bfloat16(a);
                    __nv_bfloat16 hb = __float2bfloat16(bv);
                    ph_[p2] = pack_bf2(a, bv);
                    pl_[p2] = pack_bf2(a - __bfloat162float(ha),
                                       bv - __bfloat162float(hb));
                }
                *(uint4*)(P.outH[z] + base + c8 * 8) = wh;
                *(uint4*)(P.outL[z] + base + c8 * 8) = wl;
            }
        }
    }
    __syncthreads();
    if (wid == 0) TCGEN05_DEALLOC(tmem, 512);
#else
    (void)P;
#endif
}

// ---------------------------------------------------------------------------
// Output projection GEMM (R7, SS): grid (64,4), 256 threads.
// ---------------------------------------------------------------------------
__global__ __launch_bounds__(256) void gemm_ctx_kernel(
    const __nv_bfloat16* __restrict__ Ah, const __nv_bfloat16* __restrict__ Al,
    const __nv_bfloat16* __restrict__ Bh, const __nv_bfloat16* __restrict__ Bl,
    const float* __restrict__ bias, float* __restrict__ out)
{
#if HAS_TCGEN05
    extern __shared__ __align__(1024) char smem[];
    const uint32_t sb = smem_u32(smem);
    const int tid = threadIdx.x;
    const int wid = tid >> 5, lid = tid & 31;
    const int m0 = blockIdx.x * GEMM_MT;
    const int n0 = blockIdx.y * GEMM_NT;

    if (wid == 0) TCGEN05_ALLOC(sb, 512);
    if (tid == 0) { MBARRIER_INIT(sb + 16, 1); MBARRIER_INIT(sb + 24, 1); }
    __syncthreads();
    uint32_t tmem;
    asm volatile("ld.shared.b32 %0, [%1];" : "=r"(tmem) : "r"(sb));

    uint4 rAh[4], rAl[4], rBh[8], rBl[8];
    auto ldA = [&](int k0) {
#pragma unroll
        for (int it = 0; it < 4; it++) {
            int idx = tid + it * 256;
            int row = idx >> 3, q = idx & 7;
            rAh[it] = *((const uint4*)(Ah + (size_t)(m0 + row) * NE + k0) + q);
            rAl[it] = *((const uint4*)(Al + (size_t)(m0 + row) * NE + k0) + q);
        }
    };
    auto stA = [&](char* sh, char* sl) {
#pragma unroll
        for (int it = 0; it < 4; it++) {
            int idx = tid + it * 256;
            int row = idx >> 3, q = idx & 7;
            uint32_t off = (uint32_t)(row * 128 + q * 16);
            off ^= (off >> 3) & 0x70;
            *(uint4*)(sh + off) = rAh[it];
            *(uint4*)(sl + off) = rAl[it];
        }
    };
    ldA(0);
    ld_regs_b<8>(Bh, n0, 0, rBh, tid);
    ld_regs_b<8>(Bl, n0, 0, rBl, tid);

    int ph0 = 0, ph1 = 0;
    for (int c = 0; c < 16; c++) {
        const int buf = c & 1;
        char* bs = smem + 1024 + buf * GEMM_BUF_BYTES;
        if (c >= 2) {
            if (buf == 0) { MBARRIER_WAIT_PARITY(sb + 16, ph0); ph0 ^= 1; }
            else          { MBARRIER_WAIT_PARITY(sb + 24, ph1); ph1 ^= 1; }
        }
        stA(bs, bs + 16384);
        st_regs_b<8>(bs + 32768, rBh, tid);
        st_regs_b<8>(bs + 65536, rBl, tid);
        if (c < 15) {
            const int k1 = (c + 1) * 64;
            ldA(k1);
            ld_regs_b<8>(Bh, n0, k1, rBh, tid);
            ld_regs_b<8>(Bl, n0, k1, rBl, tid);
        }
        __syncthreads();
        if (wid == 0 && elect_one())
            gemm_issue(tmem, sb + 1024 + buf * GEMM_BUF_BYTES, c == 0,
                       sb + 16 + buf * 8);
    }
    MBARRIER_WAIT_PARITY(sb + 16, ph0);
    MBARRIER_WAIT_PARITY(sb + 24, ph1);
    TCGEN05_FENCE_AFTER();

    const int m = m0 + 32 * (wid & 3) + lid;
    const int chalf = (wid >> 2) * 128;
#pragma unroll
    for (int i = 0; i < 4; i++) {
        uint32_t r[32];
        TCGEN05_LD_X32(r, tmem + chalf + i * 32);
        TCGEN05_WAIT_LD();
        const int nbase = n0 + chalf + i * 32;
        const float4* bp = (const float4*)(bias + nbase);
        float* dst = out + ((size_t)m * NE + nbase);
#pragma unroll
        for (int j4 = 0; j4 < 8; j4++) {
            float4 bb = bp[j4];
            float4 w;
            w.x = __uint_as_float(r[j4 * 4 + 0]) + bb.x;
            w.y = __uint_as_float(r[j4 * 4 + 1]) + bb.y;
            w.z = __uint_as_float(r[j4 * 4 + 2]) + bb.z;
            w.w = __uint_as_float(r[j4 * 4 + 3]) + bb.w;
            *(float4*)(dst + j4 * 4) = w;
        }
    }
    __syncthreads();
    if (wid == 0) TCGEN05_DEALLOC(tmem, 512);
#else
    (void)Ah;(void)Al;(void)Bh;(void)Bl;(void)bias;(void)out;
#endif
}

// ---------------------------------------------------------------------------
// tcgen05 flash attention: R7 synchronization structure (single S buffer,
// S(t+1)+O(t) issued together after P-sync, 3-stage KV), remapped to
// 256 threads: thread -> (row = (wid&3)*32+lid, col-half = wid>>2).
// TMEM: S cols 0-63, O cols 64-127.
// ---------------------------------------------------------------------------
#define AT_Q   1024
#define AT_QL  (AT_Q + 16384)
#define AT_STG (AT_QL + 16384)          // 3 stages x 32KB: Kh,Kl,Vh,Vl
#define AT_PH  (AT_STG + 3 * 32768)
#define AT_PL  (AT_PH + 16384)
#define AT_SMEM_BYTES (AT_PL + 16384)   // ~161KB
#define AT_IDESC ((1u<<4)|(1u<<7)|(1u<<10)|((64/8)<<17)|((128/16)<<24))

__global__ __launch_bounds__(256) void attn_mma_kernel(
    const __nv_bfloat16* __restrict__ qh, const __nv_bfloat16* __restrict__ ql,
    const __nv_bfloat16* __restrict__ kh, const __nv_bfloat16* __restrict__ kl,
    const __nv_bfloat16* __restrict__ vth, const __nv_bfloat16* __restrict__ vtl,
    const float* __restrict__ bias,
    __nv_bfloat16* __restrict__ ctx_h, __nv_bfloat16* __restrict__ ctx_l)
{
#if HAS_TCGEN05
    extern __shared__ __align__(1024) char smem[];
    const uint32_t sb = smem_u32(smem);
    const int tid = threadIdx.x;
    const int wid = tid >> 5, lid = tid & 31;
    const int s0 = blockIdx.x * 128;
    const int bh = blockIdx.y;

    const __nv_bfloat16* qhp = qh + ((size_t)bh * NS + s0) * ND;
    const __nv_bfloat16* qlp = ql + ((size_t)bh * NS + s0) * ND;
    const __nv_bfloat16* khp = kh + (size_t)bh * NS * ND;
    const __nv_bfloat16* klp = kl + (size_t)bh * NS * ND;
    const __nv_bfloat16* vhp = vth + (size_t)bh * ND * NS;
    const __nv_bfloat16* vlp = vtl + (size_t)bh * ND * NS;

    if (wid == 0) TCGEN05_ALLOC(sb, 128);
    if (tid == 0) { MBARRIER_INIT(sb + 16, 1); MBARRIER_INIT(sb + 24, 1); }
    __syncthreads();
    uint32_t tmem;
    asm volatile("ld.shared.b32 %0, [%1];" : "=r"(tmem) : "r"(sb));

    // Q tiles (hi/lo), swizzled: 1024 uint4 each -> 4 iters x 256 threads
#pragma unroll
    for (int it = 0; it < 4; it++) {
        int idx = tid + it * 256;
        int row = idx >> 3, q = idx & 7;
        uint32_t off = (uint32_t)(row * 128 + q * 16);
        off ^= (off >> 3) & 0x70;
        *(uint4*)(smem + AT_Q + off)  = *((const uint4*)(qhp + (size_t)row * ND) + q);
        *(uint4*)(smem + AT_QL + off) = *((const uint4*)(qlp + (size_t)row * ND) + q);
    }

    auto ld_kv = [&](int t, int stg) {
        char* ks = smem + AT_STG + stg * 32768;
        const __nv_bfloat16* kh_t = khp + (size_t)t * 64 * ND;
        const __nv_bfloat16* kl_t = klp + (size_t)t * 64 * ND;
        const __nv_bfloat16* vh_t = vhp + (size_t)t * 64;
        const __nv_bfloat16* vl_t = vlp + (size_t)t * 64;
#pragma unroll
        for (int it = 0; it < 2; it++) {
            int idx = tid + it * 256;
            int row = idx >> 3, q = idx & 7;
            uint32_t off = (uint32_t)(row * 128 + q * 16);
            off ^= (off >> 3) & 0x70;
            *(uint4*)(ks + off)         = *((const uint4*)(kh_t + (size_t)row * ND) + q);
            *(uint4*)(ks + 8192 + off)  = *((const uint4*)(kl_t + (size_t)row * ND) + q);
            *(uint4*)(ks + 16384 + off) = *((const uint4*)(vh_t + (size_t)row * NS) + q);
            *(uint4*)(ks + 24576 + off) = *((const uint4*)(vl_t + (size_t)row * NS) + q);
        }
    };

    const uint64_t dq_h = make_desc(sb + AT_Q);
    const uint64_t dq_l = make_desc(sb + AT_QL);
    const uint64_t dp_h = make_desc(sb + AT_PH);
    const uint64_t dp_l = make_desc(sb + AT_PL);

    // S(t) overwrites its accumulator each tile: enable = (s4 > 0) ONLY.
    auto issue_S = [&](int t) {
        const uint32_t ks = sb + AT_STG + (t % 3) * 32768;
        uint64_t dk_h = make_desc(ks), dk_l = make_desc(ks + 8192);
#pragma unroll
        for (int s4 = 0; s4 < 4; s4++) {
            uint64_t o2 = 2u * s4;
            mma_f16_ss(tmem, dq_h + o2, dk_h + o2, AT_IDESC, s4 > 0 ? 1u : 0u);
            mma_f16_ss(tmem, dq_l + o2, dk_h + o2, AT_IDESC, 1u);
            mma_f16_ss(tmem, dq_h + o2, dk_l + o2, AT_IDESC, 1u);
        }
    };
    auto issue_O = [&](int t) {
        const uint32_t ks = sb + AT_STG + (t % 3) * 32768;
        uint64_t dv_h = make_desc(ks + 16384), dv_l = make_desc(ks + 24576);
#pragma unroll
        for (int s4 = 0; s4 < 4; s4++) {
            uint64_t o2 = 2u * s4;
            mma_f16_ss(tmem + 64, dp_h + o2, dv_h + o2, AT_IDESC,
                       (t > 0 || s4 > 0) ? 1u : 0u);
            mma_f16_ss(tmem + 64, dp_l + o2, dv_h + o2, AT_IDESC, 1u);
            mma_f16_ss(tmem + 64, dp_h + o2, dv_l + o2, AT_IDESC, 1u);
        }
    };

    ld_kv(0, 0);
    __syncthreads();
    if (wid == 0 && elect_one()) {
        FENCE_ASYNC();
        issue_S(0);
        TCGEN05_COMMIT(sb + 16);
    }

    // thread -> (row, half): row = (wid&3)*32 + lid, half = wid>>2
    const int srow = (wid & 3) * 32 + lid;
    const int shf = wid >> 2;
    const float* brow = bias + (size_t)(s0 + srow) * NS;
    float lsum = 0.f;
    int ph_s = 0, ph_o = 0;

    for (int t = 0; t < 32; t++) {
        if (t + 1 < 32) ld_kv(t + 1, (t + 1) % 3);

        float4 bb[8];
        const float4* bp = (const float4*)(brow + t * 64 + shf * 32);
#pragma unroll
        for (int i = 0; i < 8; i++) bb[i] = bp[i];

        MBARRIER_WAIT_PARITY(sb + 16, ph_s);   // S(t) done
        ph_s ^= 1;
        TCGEN05_FENCE_AFTER();

        uint32_t r[32];
        TCGEN05_LD_X32(r, tmem + shf * 32);
        TCGEN05_WAIT_LD();
        float p[32];
#pragma unroll
        for (int j4 = 0; j4 < 8; j4++) {
            float4 b4 = bb[j4];
            p[j4*4+0] = __expf(fmaf(__uint_as_float(r[j4*4+0]), 0.125f, b4.x));
            p[j4*4+1] = __expf(fmaf(__uint_as_float(r[j4*4+1]), 0.125f, b4.y));
            p[j4*4+2] = __expf(fmaf(__uint_as_float(r[j4*4+2]), 0.125f, b4.z));
            p[j4*4+3] = __expf(fmaf(__uint_as_float(r[j4*4+3]), 0.125f, b4.w));
            lsum += p[j4*4+0] + p[j4*4+1] + p[j4*4+2] + p[j4*4+3];
        }

        if (t >= 1) {                          // O(t-1) done reading P
            MBARRIER_WAIT_PARITY(sb + 24, ph_o);
            ph_o ^= 1;
        }
#pragma unroll
        for (int c4 = 0; c4 < 4; c4++) {
            uint4 wh, wl;
            uint32_t* phh = &wh.x;
            uint32_t* pll = &wl.x;
#pragma unroll
            for (int p2 = 0; p2 < 4; p2++) {
                float a = p[c4 * 8 + p2 * 2];
                float c = p[c4 * 8 + p2 * 2 + 1];
                __nv_bfloat16 ha = __float2bfloat16(a);
                __nv_bfloat16 hc = __float2bfloat16(c);
                phh[p2] = pack_bf2(a, c);
                pll[p2] = pack_bf2(a - __bfloat162float(ha),
                                   c - __bfloat162float(hc));
            }
            uint32_t off = (uint32_t)(srow * 128 + shf * 64 + c4 * 16);
            off ^= (off >> 3) & 0x70;
            *(uint4*)(smem + AT_PH + off) = wh;
            *(uint4*)(smem + AT_PL + off) = wl;
        }
        TCGEN05_FENCE_BEFORE();
        __syncthreads();                        // P + KV(t+1) visible

        if (wid == 0 && elect_one()) {
            FENCE_ASYNC();
            if (t + 1 < 32) {
                issue_S(t + 1);
                TCGEN05_COMMIT(sb + 16);       // bar_s: S(t+1)
            }
            issue_O(t);
            TCGEN05_COMMIT(sb + 24);           // bar_o: O(t)
        }
    }
    MBARRIER_WAIT_PARITY(sb + 24, ph_o);       // O(31)
    TCGEN05_FENCE_AFTER();

    // merge lsum halves via smem (P region dead after O(31))
    *(float*)(smem + AT_PH + tid * 4) = lsum;
    __syncthreads();
    const float lother = *(const float*)(smem + AT_PH + (tid ^ 128) * 4);
    const float inv = 1.f / (lsum + lother);

    const int b = bh >> 4, h = bh & 15;
    const size_t obase = ((size_t)b * NS + s0 + srow) * NE + h * ND + shf * 32;
    uint32_t r[32];
    TCGEN05_LD_X32(r, tmem + 64 + shf * 32);
    TCGEN05_WAIT_LD();
#pragma unroll
    for (int c8 = 0; c8 < 4; c8++) {
        uint4 wh, wl;
        uint32_t* phh = &wh.x;
        uint32_t* pll = &wl.x;
#pragma unroll
        for (int p2 = 0; p2 < 4; p2++) {
            float a = __uint_as_float(r[c8 * 8 + p2 * 2]) * inv;
            float c = __uint_as_float(r[c8 * 8 + p2 * 2 + 1]) * inv;
            __nv_bfloat16 ha = __float2bfloat16(a);
            __nv_bfloat16 hc = __float2bfloat16(c);
            phh[p2] = pack_bf2(a, c);
            pll[p2] = pack_bf2(a - __bfloat162float(ha),
                               c - __bfloat162float(hc));
        }
        *(uint4*)(ctx_h + obase + c8 * 8) = wh;
        *(uint4*)(ctx_l + obase + c8 * 8) = wl;
    }
    TCGEN05_FENCE_BEFORE();
    __syncthreads();
    if (wid == 0) TCGEN05_DEALLOC(tmem, 128);
#else
    (void)qh;(void)ql;(void)kh;(void)kl;(void)vth;(void)vtl;(void)bias;(void)ctx_h;(void)ctx_l;
#endif
}

// ---------------------------------------------------------------------------
// transpose + split: in[z][R][C] fp32 -> out[(z*C + c)][R] bf16 hi/lo
// ---------------------------------------------------------------------------
__global__ __launch_bounds__(256) void transpose_split_kernel(
    const float* __restrict__ in, __nv_bfloat16* __restrict__ oh,
    __nv_bfloat16* __restrict__ ol, int C, int R)
{
    __shared__ float t[64][65];
    const float* inz = in + (size_t)blockIdx.z * R * C;
    const int r0 = blockIdx.x * 64, c0 = blockIdx.y * 64;
    const int tid = threadIdx.x;
#pragma unroll
    for (int it = 0; it < 16; it++) {
        int idx = tid + it * 256;
        int rr = idx >> 6, cc = idx & 63;
        t[rr][cc] = inz[(size_t)(r0 + rr) * C + c0 + cc];
    }
    __syncthreads();
#pragma unroll
    for (int it = 0; it < 16; it++) {
        int idx = tid + it * 256;
        int cc = idx >> 6, rr = idx & 63;
        float x = t[rr][cc];
        __nv_bfloat16 hi = __float2bfloat16(x);
        size_t o = (size_t)(blockIdx.z * C + c0 + cc) * R + r0 + rr;
        oh[o] = hi;
        ol[o] = __float2bfloat16(x - __bfloat162float(hi));
    }
}

// ---------------------------------------------------------------------------

extern "C" void kernel_launch(void* const* d_in, const int* in_sizes, int n_in,
                              void* d_out, int out_size)
{
    const float* query = (const float*)d_in[0];
    const float* key_  = (const float*)d_in[1];
    const float* value = (const float*)d_in[2];
    const float* abias = (const float*)d_in[3];
    const float* Wq = (const float*)d_in[4];
    const float* bq = (const float*)d_in[5];
    const float* Wk = (const float*)d_in[6];
    const float* bk = (const float*)d_in[7];
    const float* Wv = (const float*)d_in[8];
    const float* bv = (const float*)d_in[9];
    const float* Wo = (const float*)d_in[10];
    const float* bo = (const float*)d_in[11];
    float* out = (float*)d_out;

    float* vp;
    __nv_bfloat16 *qh, *ql, *kh, *kl, *vth, *vtl, *ah, *al, *wth, *wtl;
    cudaGetSymbolAddress((void**)&vp, g_v);
    cudaGetSymbolAddress((void**)&qh, g_qh);
    cudaGetSymbolAddress((void**)&ql, g_ql);
    cudaGetSymbolAddress((void**)&kh, g_kh);
    cudaGetSymbolAddress((void**)&kl, g_kl);
    cudaGetSymbolAddress((void**)&vth, g_vth);
    cudaGetSymbolAddress((void**)&vtl, g_vtl);
    cudaGetSymbolAddress((void**)&ah, g_ah);
    cudaGetSymbolAddress((void**)&al, g_al);
    cudaGetSymbolAddress((void**)&wth, g_wth);
    cudaGetSymbolAddress((void**)&wtl, g_wtl);

    cudaFuncSetAttribute(gemm_qkv_kernel,
                         cudaFuncAttributeMaxDynamicSharedMemorySize,
                         GEMM_SMEM_BYTES);
    cudaFuncSetAttribute(gemm_ctx_kernel,
                         cudaFuncAttributeMaxDynamicSharedMemorySize,
                         GEMM_SMEM_BYTES);
    cudaFuncSetAttribute(attn_mma_kernel,
                         cudaFuncAttributeMaxDynamicSharedMemorySize,
                         AT_SMEM_BYTES);

    // weight transposes (hi/lo)
    dim3 gw(16, 1, 16);
    transpose_split_kernel<<<gw, 256>>>(Wq, wth + 0 * NE * NE, wtl + 0 * NE * NE, ND, NE);
    transpose_split_kernel<<<gw, 256>>>(Wk, wth + 1 * NE * NE, wtl + 1 * NE * NE, ND, NE);
    transpose_split_kernel<<<gw, 256>>>(Wv, wth + 2 * NE * NE, wtl + 2 * NE * NE, ND, NE);

    // fused QKV projections
    QKVParams P;
    P.A[0] = query; P.A[1] = key_; P.A[2] = value;
    P.Wh[0] = wth; P.Wh[1] = wth + NE * NE; P.Wh[2] = wth + 2 * NE * NE;
    P.Wl[0] = wtl; P.Wl[1] = wtl + NE * NE; P.Wl[2] = wtl + 2 * NE * NE;
    P.bias[0] = bq; P.bias[1] = bk; P.bias[2] = bv;
    P.outV = vp;
    P.outH[0] = qh; P.outH[1] = kh;
    P.outL[0] = ql; P.outL[1] = kl;
    gemm_qkv_kernel<<<dim3(64, 4, 3), 256, GEMM_SMEM_BYTES>>>(P);

    // V^T split for PV MMA
    transpose_split_kernel<<<dim3(32, 1, 64), 256>>>(vp, vth, vtl, ND, NS);

    // attention -> ctx bf16 hi/lo
    attn_mma_kernel<<<dim3(16, 64), 256, AT_SMEM_BYTES>>>(
        qh, ql, kh, kl, vth, vtl, abias, ah, al);

    // output projection
    transpose_split_kernel<<<dim3(16, 16, 1), 256>>>(Wo, wth, wtl, NE, NE);
    gemm_ctx_kernel<<<dim3(64, 4), 256, GEMM_SMEM_BYTES>>>(ah, al, wth, wtl, bo, out);
}